// round 7
// baseline (speedup 1.0000x reference)
#include <cuda_runtime.h>
#include <cuda_bf16.h>
#include <cstdint>
#include <cstddef>
#include <math.h>

// Problem constants (fixed by setup_inputs)
#define BB   8
#define LL   273
#define DIM  1536
#define NH   12
#define HD   128
#define ZS   256
#define FH   32
#define MTOT (BB * LL)   // 2184

// ---------------- scratch (no allocations allowed) ----------------
__device__ float g_qbuf[(size_t)MTOT * DIM];
__device__ float g_kbuf[(size_t)MTOT * DIM];
__device__ float g_vbuf[(size_t)MTOT * DIM];
__device__ float g_abuf[(size_t)MTOT * DIM];

// ===================== TF32 tensor-core GEMM (ldmatrix edition) ============
// C[m,n] = sum_k A[m,k] * W[n,k] + bias[n]
// Block tile 128x128, BK=32. 8 warps in 2(m) x 4(n); warp tile 64x32.
// Inner loop: ldmatrix.m8n8.x4 fragment loads + mma.m16n8k8.tf32.
// tf32 conversion (cvt.rna) happens once per element on the STS path.

#define GBM 128
#define GBN 128
#define GBK 32
#define SPAD 36   // padded row (floats): conflict-free LDS/ldmatrix

__device__ __forceinline__ unsigned f2tf32(float f) {
    unsigned r;
    asm("cvt.rna.tf32.f32 %0, %1;" : "=r"(r) : "f"(f));
    return r;
}

__device__ __forceinline__ void mma_tf32(float* c, const unsigned* a, const unsigned* b) {
    asm volatile(
        "mma.sync.aligned.m16n8k8.row.col.f32.tf32.tf32.f32 "
        "{%0,%1,%2,%3}, {%4,%5,%6,%7}, {%8,%9}, {%0,%1,%2,%3};"
        : "+f"(c[0]), "+f"(c[1]), "+f"(c[2]), "+f"(c[3])
        : "r"(a[0]), "r"(a[1]), "r"(a[2]), "r"(a[3]),
          "r"(b[0]), "r"(b[1]));
}

__device__ __forceinline__ void ldmatrix_x4(unsigned* r, unsigned addr) {
    asm volatile("ldmatrix.sync.aligned.m8n8.x4.shared.b16 {%0,%1,%2,%3}, [%4];"
                 : "=r"(r[0]), "=r"(r[1]), "=r"(r[2]), "=r"(r[3]) : "r"(addr));
}

// SPLIT: A row r comes from A2 when (r % LL) >= ZS, else A1.
template <bool SPLIT>
__device__ __forceinline__ void gemm_body(
    const float* __restrict__ A1, const float* __restrict__ A2,
    const float* __restrict__ W,
    const float* __restrict__ bias, float* __restrict__ C, int Mrows)
{
    __shared__ float As[GBM * SPAD];
    __shared__ float Bs[GBN * SPAD];

    const int bm = blockIdx.y * GBM;
    const int bn = blockIdx.x * GBN;
    const int tid  = threadIdx.x;
    const int lane = tid & 31;
    const int warp = tid >> 5;
    const int wm = warp >> 2;        // 0..1  -> 64 rows
    const int wn = warp & 3;         // 0..3  -> 32 cols

    const int ldr = tid >> 3;            // 0..31 base row
    const int ldc = (tid & 7) << 2;      // k offset (floats)

    // ---- per-thread gmem row pointers ----
    const float* aptr[4];
    bool aok[4];
#pragma unroll
    for (int i = 0; i < 4; i++) {
        int gr = bm + ldr + i * 32;
        aok[i] = (gr < Mrows);
        int grc = aok[i] ? gr : (Mrows - 1);
        const float* base = A1;
        if (SPLIT && (grc % LL) >= ZS) base = A2;
        aptr[i] = base + (size_t)grc * DIM + ldc;
    }
    const float* wptr[4];
#pragma unroll
    for (int i = 0; i < 4; i++)
        wptr[i] = W + (size_t)(bn + ldr + i * 32) * DIM + ldc;

    // ---- ldmatrix per-lane addresses ----
    const unsigned asb = (unsigned)__cvta_generic_to_shared(As);
    const unsigned bsb = (unsigned)__cvta_generic_to_shared(Bs);
    const int lm = lane >> 3;    // matrix index 0..3
    const int lr = lane & 7;     // row within matrix
    unsigned aaddr[4];           // per mt: m16 x k8 (4 matrices: r/r+8 x k/k+4)
#pragma unroll
    for (int mt = 0; mt < 4; mt++) {
        int row = wm * 64 + mt * 16 + (lm & 1) * 8 + lr;
        int col = (lm >> 1) * 4;
        aaddr[mt] = asb + (unsigned)(row * SPAD + col) * 4u;
    }
    unsigned baddr[2];           // per pair p: n16 x k8 (4 matrices: (n,k),(n,k+4),(n+8,k),(n+8,k+4))
#pragma unroll
    for (int p = 0; p < 2; p++) {
        int row = wn * 32 + p * 16 + (lm >> 1) * 8 + lr;
        int col = (lm & 1) * 4;
        baddr[p] = bsb + (unsigned)(row * SPAD + col) * 4u;
    }

    float acc[4][4][4];
#pragma unroll
    for (int i = 0; i < 4; i++)
#pragma unroll
        for (int j = 0; j < 4; j++)
#pragma unroll
            for (int r = 0; r < 4; r++) acc[i][j][r] = 0.f;

    const int NT = DIM / GBK;   // 48

    // ---- prefetch tile 0 into registers ----
    float4 areg[4], breg[4];
#pragma unroll
    for (int i = 0; i < 4; i++) {
        areg[i] = aok[i] ? *(const float4*)(aptr[i]) : make_float4(0.f, 0.f, 0.f, 0.f);
        breg[i] = *(const float4*)(wptr[i]);
    }

    for (int t = 0; t < NT; t++) {
        // ---- store prefetched tile to smem (with tf32 rounding) ----
#pragma unroll
        for (int i = 0; i < 4; i++) {
            uint4 av, bv;
            av.x = f2tf32(areg[i].x); av.y = f2tf32(areg[i].y);
            av.z = f2tf32(areg[i].z); av.w = f2tf32(areg[i].w);
            bv.x = f2tf32(breg[i].x); bv.y = f2tf32(breg[i].y);
            bv.z = f2tf32(breg[i].z); bv.w = f2tf32(breg[i].w);
            *(uint4*)&As[(ldr + i * 32) * SPAD + ldc] = av;
            *(uint4*)&Bs[(ldr + i * 32) * SPAD + ldc] = bv;
        }
        __syncthreads();

        // ---- prefetch next tile ----
        if (t + 1 < NT) {
            const int koff = (t + 1) * GBK;
#pragma unroll
            for (int i = 0; i < 4; i++) {
                areg[i] = aok[i] ? *(const float4*)(aptr[i] + koff) : make_float4(0.f, 0.f, 0.f, 0.f);
                breg[i] = *(const float4*)(wptr[i] + koff);
            }
        }

        // ---- compute on resident tile ----
#pragma unroll
        for (int kk = 0; kk < GBK / 8; kk++) {
            const unsigned koffb = (unsigned)(kk * 8 * 4);   // 8 floats = 32 bytes
            unsigned afrag[4][4];
            unsigned bfrag[4][2];
#pragma unroll
            for (int mt = 0; mt < 4; mt++)
                ldmatrix_x4(afrag[mt], aaddr[mt] + koffb);
#pragma unroll
            for (int p = 0; p < 2; p++) {
                unsigned v[4];
                ldmatrix_x4(v, baddr[p] + koffb);
                bfrag[2 * p][0] = v[0]; bfrag[2 * p][1] = v[1];
                bfrag[2 * p + 1][0] = v[2]; bfrag[2 * p + 1][1] = v[3];
            }
#pragma unroll
            for (int mt = 0; mt < 4; mt++)
#pragma unroll
                for (int nt = 0; nt < 4; nt++)
                    mma_tf32(acc[mt][nt], afrag[mt], bfrag[nt]);
        }
        __syncthreads();
    }

    // ---- epilogue ----
    const int rsel = lane >> 2;
    const int csel = (lane & 3) * 2;
#pragma unroll
    for (int mt = 0; mt < 4; mt++) {
#pragma unroll
        for (int nt = 0; nt < 4; nt++) {
            int col = bn + wn * 32 + nt * 8 + csel;
            float b0 = bias[col], b1 = bias[col + 1];
            int r0 = bm + wm * 64 + mt * 16 + rsel;
            if (r0 < Mrows) {
                float2 o; o.x = acc[mt][nt][0] + b0; o.y = acc[mt][nt][1] + b1;
                *(float2*)(C + (size_t)r0 * DIM + col) = o;
            }
            if (r0 + 8 < Mrows) {
                float2 o; o.x = acc[mt][nt][2] + b0; o.y = acc[mt][nt][3] + b1;
                *(float2*)(C + (size_t)(r0 + 8) * DIM + col) = o;
            }
        }
    }
}

// Fused QKV: blockIdx.z selects which projection
__global__ __launch_bounds__(256)
void gemm_qkv(const float* __restrict__ x,
              const float* __restrict__ w_q, const float* __restrict__ b_q,
              const float* __restrict__ w_k, const float* __restrict__ b_k,
              const float* __restrict__ w_v, const float* __restrict__ b_v)
{
    const float* W; const float* bias; float* C;
    if (blockIdx.z == 0)      { W = w_q; bias = b_q; C = g_qbuf; }
    else if (blockIdx.z == 1) { W = w_k; bias = b_k; C = g_kbuf; }
    else                      { W = w_v; bias = b_v; C = g_vbuf; }
    gemm_body<false>(x, x, W, bias, C, MTOT);
}

// Output projection. A rows: attention out for z<ZS, raw v for z>=ZS.
__global__ __launch_bounds__(256)
void gemm_out(const float* __restrict__ w_o, const float* __restrict__ b_o,
              float* __restrict__ out)
{
    gemm_body<true>(g_abuf, g_vbuf, w_o, b_o, out, MTOT);
}

// ---------------- rmsnorm over full DIM row (applied to q and k buffers) ----
__global__ __launch_bounds__(256)
void rmsnorm_kernel(const float* __restrict__ gq, const float* __restrict__ gk)
{
    int row = blockIdx.x;            // 0..2*MTOT-1
    float* buf;
    const float* g;
    if (row < MTOT) { buf = g_qbuf + (size_t)row * DIM; g = gq; }
    else            { buf = g_kbuf + (size_t)(row - MTOT) * DIM; g = gk; }

    int tid = threadIdx.x;
    float ss = 0.f;
    float vals[6];
#pragma unroll
    for (int i = 0; i < 6; i++) {
        vals[i] = buf[tid + i * 256];
        ss += vals[i] * vals[i];
    }
    __shared__ float sred[8];
    int lane = tid & 31, warp = tid >> 5;
#pragma unroll
    for (int off = 16; off; off >>= 1) ss += __shfl_xor_sync(0xffffffffu, ss, off);
    if (lane == 0) sred[warp] = ss;
    __syncthreads();
    if (warp == 0) {
        float v = (lane < 8) ? sred[lane] : 0.f;
#pragma unroll
        for (int off = 4; off; off >>= 1) v += __shfl_xor_sync(0xffffffffu, v, off);
        if (lane == 0) sred[0] = v;
    }
    __syncthreads();
    float inv = rsqrtf(sred[0] / (float)DIM + 1e-6f);
#pragma unroll
    for (int i = 0; i < 6; i++)
        buf[tid + i * 256] = vals[i] * inv * g[tid + i * 256];
}

// ---------------- attention: one block per (b, z<ZS, n) ----------------
__global__ __launch_bounds__(128)
void attn_kernel(const float* __restrict__ cache_k, const float* __restrict__ cache_v,
                 const float* __restrict__ rope_table,
                 const int* __restrict__ rridx, const int* __restrict__ cfi_p)
{
    const int bx = blockIdx.x;
    const int n = bx % NH;
    const int z = (bx / NH) % ZS;
    const int b = bx / (NH * ZS);

    const int tid  = threadIdx.x;
    const int lane = tid & 31;
    const int warp = tid >> 5;

    const int cfi   = cfi_p[0];
    const int slot  = cfi % FH;
    const int valid = min(cfi + 1, FH);

    __shared__ float qr[HD];
    __shared__ float prob[FH];

    // rope q with freqs_last = rope_table[cfi, z, :]
    if (tid < HD / 2) {
        int i = tid;
        float f = rope_table[((size_t)cfi * LL + z) * (HD / 2) + i];
        float c = cosf(f), s = sinf(f);
        const float* qp = g_qbuf + (((size_t)(b * LL + z)) * NH + n) * HD;
        float q0 = qp[2 * i], q1 = qp[2 * i + 1];
        qr[2 * i]     = q0 * c - q1 * s;
        qr[2 * i + 1] = q0 * s + q1 * c;
    }
    __syncthreads();

    // scores: warp per frame (strided)
    const float scale = 0.08838834764831845f;  // 1/sqrt(128)
    for (int g = warp; g < valid; g += 4) {
        const float* kp;
        if (g == slot)
            kp = g_kbuf + (((size_t)(b * LL + z)) * NH + n) * HD;
        else
            kp = cache_k + ((((size_t)b * FH + g) * LL + z) * NH + n) * HD;
        int d0 = lane * 4;
        float4 kv = *(const float4*)(kp + d0);
        int ri = rridx[g];
        const float* fp = rope_table + ((size_t)ri * LL + z) * (HD / 2) + (d0 >> 1);
        float f0 = fp[0], f1 = fp[1];
        float c0 = cosf(f0), s0 = sinf(f0);
        float c1 = cosf(f1), s1 = sinf(f1);
        float kr0 = kv.x * c0 - kv.y * s0;
        float kr1 = kv.x * s0 + kv.y * c0;
        float kr2 = kv.z * c1 - kv.w * s1;
        float kr3 = kv.z * s1 + kv.w * c1;
        float p = qr[d0] * kr0 + qr[d0 + 1] * kr1 + qr[d0 + 2] * kr2 + qr[d0 + 3] * kr3;
#pragma unroll
        for (int off = 16; off; off >>= 1) p += __shfl_xor_sync(0xffffffffu, p, off);
        if (lane == 0) prob[g] = p * scale;
    }
    __syncthreads();

    // softmax over g<valid (warp 0)
    if (warp == 0) {
        float v = (lane < valid) ? prob[lane] : -INFINITY;
        float m = v;
#pragma unroll
        for (int off = 16; off; off >>= 1) m = fmaxf(m, __shfl_xor_sync(0xffffffffu, m, off));
        float e = (lane < valid) ? expf(v - m) : 0.f;
        float ssum = e;
#pragma unroll
        for (int off = 16; off; off >>= 1) ssum += __shfl_xor_sync(0xffffffffu, ssum, off);
        if (lane < FH) prob[lane] = e / ssum;
    }
    __syncthreads();

    // output: thread per d
    int d = tid;
    float acc = 0.f;
    for (int g = 0; g < valid; g++) {
        const float* vp;
        if (g == slot)
            vp = g_vbuf + (((size_t)(b * LL + z)) * NH + n) * HD;
        else
            vp = cache_v + ((((size_t)b * FH + g) * LL + z) * NH + n) * HD;
        acc = fmaf(prob[g], vp[d], acc);
    }
    g_abuf[((size_t)(b * LL + z)) * DIM + n * HD + d] = acc;
}

// ---------------- launch ----------------
extern "C" void kernel_launch(void* const* d_in, const int* in_sizes, int n_in,
                              void* d_out, int out_size)
{
    const float* x      = (const float*)d_in[0];
    const float* w_q    = (const float*)d_in[1];
    const float* b_q    = (const float*)d_in[2];
    const float* w_k    = (const float*)d_in[3];
    const float* b_k    = (const float*)d_in[4];
    const float* w_v    = (const float*)d_in[5];
    const float* b_v    = (const float*)d_in[6];
    const float* w_o    = (const float*)d_in[7];
    const float* b_o    = (const float*)d_in[8];
    const float* g_q    = (const float*)d_in[9];
    const float* g_k    = (const float*)d_in[10];
    const float* cache_k= (const float*)d_in[11];
    const float* cache_v= (const float*)d_in[12];
    const float* rope_t = (const float*)d_in[13];
    const int*   rridx  = (const int*)d_in[14];
    const int*   cfi    = (const int*)d_in[15];
    float*       out    = (float*)d_out;

    dim3 qkvgrid(DIM / GBN, (MTOT + GBM - 1) / GBM, 3);   // (12, 18, 3)
    gemm_qkv<<<qkvgrid, 256>>>(x, w_q, b_q, w_k, b_k, w_v, b_v);

    rmsnorm_kernel<<<2 * MTOT, 256>>>(g_q, g_k);

    attn_kernel<<<BB * ZS * NH, 128>>>(cache_k, cache_v, rope_t, rridx, cfi);

    dim3 ogrid(DIM / GBN, (MTOT + GBM - 1) / GBM);        // (12, 18)
    gemm_out<<<ogrid, 256>>>(w_o, b_o, out);
}

// round 9
// speedup vs baseline: 1.2358x; 1.2358x over previous
#include <cuda_runtime.h>
#include <cuda_bf16.h>
#include <cuda_fp16.h>
#include <cstdint>
#include <cstddef>
#include <math.h>

// Problem constants (fixed by setup_inputs)
#define BB   8
#define LL   273
#define DIM  1536
#define NH   12
#define HD   128
#define ZS   256
#define FH   32
#define MTOT (BB * LL)   // 2184

// ---------------- scratch (no allocations allowed) ----------------
__device__ float g_qbuf[(size_t)MTOT * DIM];
__device__ float g_kbuf[(size_t)MTOT * DIM];
__device__ float g_vbuf[(size_t)MTOT * DIM];
__device__ float g_abuf[(size_t)MTOT * DIM];

// ===================== FP16 tensor-core GEMM =====================
// C[m,n] = sum_k A[m,k] * W[n,k] + bias[n],  fp32 accumulate.
// Block tile 128x128, BK=32. 8 warps in 2(m) x 4(n); warp tile 64x32.
// Inner loop: ldmatrix.m8n8.x4.b16 + mma.sync.m16n8k16.f32.f16.f16.f32.

#define GBM 128
#define GBN 128
#define GBK 32
#define SPADH 40   // padded row length in halves (80 B stride): conflict-free ldmatrix

__device__ __forceinline__ void mma_f16(float* c, const unsigned* a, const unsigned* b) {
    asm volatile(
        "mma.sync.aligned.m16n8k16.row.col.f32.f16.f16.f32 "
        "{%0,%1,%2,%3}, {%4,%5,%6,%7}, {%8,%9}, {%0,%1,%2,%3};"
        : "+f"(c[0]), "+f"(c[1]), "+f"(c[2]), "+f"(c[3])
        : "r"(a[0]), "r"(a[1]), "r"(a[2]), "r"(a[3]),
          "r"(b[0]), "r"(b[1]));
}

__device__ __forceinline__ void ldmatrix_x4(unsigned* r, unsigned addr) {
    asm volatile("ldmatrix.sync.aligned.m8n8.x4.shared.b16 {%0,%1,%2,%3}, [%4];"
                 : "=r"(r[0]), "=r"(r[1]), "=r"(r[2]), "=r"(r[3]) : "r"(addr));
}

// SPLIT: A row r comes from A2 when (r % LL) >= ZS, else A1.
template <bool SPLIT>
__device__ __forceinline__ void gemm_body(
    const float* __restrict__ A1, const float* __restrict__ A2,
    const float* __restrict__ W,
    const float* __restrict__ bias, float* __restrict__ C, int Mrows)
{
    __shared__ __half As[GBM * SPADH];
    __shared__ __half Bs[GBN * SPADH];

    const int bm = blockIdx.y * GBM;
    const int bn = blockIdx.x * GBN;
    const int tid  = threadIdx.x;
    const int lane = tid & 31;
    const int warp = tid >> 5;
    const int wm = warp >> 2;        // 0..1  -> 64 rows
    const int wn = warp & 3;         // 0..3  -> 32 cols

    const int ldr = tid >> 3;            // 0..31 base row
    const int ldc = (tid & 7) << 2;      // k offset (elements)

    // ---- per-thread gmem row pointers ----
    const float* aptr[4];
    bool aok[4];
#pragma unroll
    for (int i = 0; i < 4; i++) {
        int gr = bm + ldr + i * 32;
        aok[i] = (gr < Mrows);
        int grc = aok[i] ? gr : (Mrows - 1);
        const float* base = A1;
        if (SPLIT && (grc % LL) >= ZS) base = A2;
        aptr[i] = base + (size_t)grc * DIM + ldc;
    }
    const float* wptr[4];
#pragma unroll
    for (int i = 0; i < 4; i++)
        wptr[i] = W + (size_t)(bn + ldr + i * 32) * DIM + ldc;

    // ---- ldmatrix per-lane addresses (byte units; halves * 2) ----
    const unsigned asb = (unsigned)__cvta_generic_to_shared(As);
    const unsigned bsb = (unsigned)__cvta_generic_to_shared(Bs);
    const int lm = lane >> 3;    // matrix index 0..3
    const int lr = lane & 7;     // row within matrix
    // A, per mt: m16 x k16. m0: r0-7/k0-7, m1: r8-15/k0-7, m2: r0-7/k8-15, m3: r8-15/k8-15
    unsigned aaddr[4];
#pragma unroll
    for (int mt = 0; mt < 4; mt++) {
        int row = wm * 64 + mt * 16 + (lm & 1) * 8 + lr;
        int col = (lm >> 1) * 8;                     // halves
        aaddr[mt] = asb + (unsigned)(row * SPADH + col) * 2u;
    }
    // B, per pair p (covers nt=2p, 2p+1): m0: n0-7/k0-7, m1: n0-7/k8-15, m2: n8-15/k0-7, m3: n8-15/k8-15
    unsigned baddr[2];
#pragma unroll
    for (int p = 0; p < 2; p++) {
        int row = wn * 32 + p * 16 + (lm >> 1) * 8 + lr;
        int col = (lm & 1) * 8;                      // halves
        baddr[p] = bsb + (unsigned)(row * SPADH + col) * 2u;
    }

    float acc[4][4][4];
#pragma unroll
    for (int i = 0; i < 4; i++)
#pragma unroll
        for (int j = 0; j < 4; j++)
#pragma unroll
            for (int r = 0; r < 4; r++) acc[i][j][r] = 0.f;

    const int NT = DIM / GBK;   // 48

    // ---- prefetch tile 0 into registers ----
    float4 areg[4], breg[4];
#pragma unroll
    for (int i = 0; i < 4; i++) {
        areg[i] = aok[i] ? *(const float4*)(aptr[i]) : make_float4(0.f, 0.f, 0.f, 0.f);
        breg[i] = *(const float4*)(wptr[i]);
    }

    for (int t = 0; t < NT; t++) {
        // ---- store prefetched tile to smem as fp16 ----
#pragma unroll
        for (int i = 0; i < 4; i++) {
            __half2 a01 = __floats2half2_rn(areg[i].x, areg[i].y);
            __half2 a23 = __floats2half2_rn(areg[i].z, areg[i].w);
            __half2 b01 = __floats2half2_rn(breg[i].x, breg[i].y);
            __half2 b23 = __floats2half2_rn(breg[i].z, breg[i].w);
            uint2 av, bv;
            av.x = *(unsigned*)&a01; av.y = *(unsigned*)&a23;
            bv.x = *(unsigned*)&b01; bv.y = *(unsigned*)&b23;
            *(uint2*)&As[(ldr + i * 32) * SPADH + ldc] = av;
            *(uint2*)&Bs[(ldr + i * 32) * SPADH + ldc] = bv;
        }
        __syncthreads();

        // ---- prefetch next tile ----
        if (t + 1 < NT) {
            const int koff = (t + 1) * GBK;
#pragma unroll
            for (int i = 0; i < 4; i++) {
                areg[i] = aok[i] ? *(const float4*)(aptr[i] + koff) : make_float4(0.f, 0.f, 0.f, 0.f);
                breg[i] = *(const float4*)(wptr[i] + koff);
            }
        }

        // ---- compute on resident tile: 2 x k16 ----
#pragma unroll
        for (int kk = 0; kk < GBK / 16; kk++) {
            const unsigned koffb = (unsigned)(kk * 16 * 2);   // 16 halves = 32 bytes
            unsigned afrag[4][4];
            unsigned bfrag[4][2];
#pragma unroll
            for (int mt = 0; mt < 4; mt++)
                ldmatrix_x4(afrag[mt], aaddr[mt] + koffb);
#pragma unroll
            for (int p = 0; p < 2; p++) {
                unsigned v[4];
                ldmatrix_x4(v, baddr[p] + koffb);
                bfrag[2 * p][0]     = v[0]; bfrag[2 * p][1]     = v[1];
                bfrag[2 * p + 1][0] = v[2]; bfrag[2 * p + 1][1] = v[3];
            }
#pragma unroll
            for (int mt = 0; mt < 4; mt++)
#pragma unroll
                for (int nt = 0; nt < 4; nt++)
                    mma_f16(acc[mt][nt], afrag[mt], bfrag[nt]);
        }
        __syncthreads();
    }

    // ---- epilogue ----
    const int rsel = lane >> 2;
    const int csel = (lane & 3) * 2;
#pragma unroll
    for (int mt = 0; mt < 4; mt++) {
#pragma unroll
        for (int nt = 0; nt < 4; nt++) {
            int col = bn + wn * 32 + nt * 8 + csel;
            float b0 = bias[col], b1 = bias[col + 1];
            int r0 = bm + wm * 64 + mt * 16 + rsel;
            if (r0 < Mrows) {
                float2 o; o.x = acc[mt][nt][0] + b0; o.y = acc[mt][nt][1] + b1;
                *(float2*)(C + (size_t)r0 * DIM + col) = o;
            }
            if (r0 + 8 < Mrows) {
                float2 o; o.x = acc[mt][nt][2] + b0; o.y = acc[mt][nt][3] + b1;
                *(float2*)(C + (size_t)(r0 + 8) * DIM + col) = o;
            }
        }
    }
}

// Fused QKV: blockIdx.z selects which projection
__global__ __launch_bounds__(256)
void gemm_qkv(const float* __restrict__ x,
              const float* __restrict__ w_q, const float* __restrict__ b_q,
              const float* __restrict__ w_k, const float* __restrict__ b_k,
              const float* __restrict__ w_v, const float* __restrict__ b_v)
{
    const float* W; const float* bias; float* C;
    if (blockIdx.z == 0)      { W = w_q; bias = b_q; C = g_qbuf; }
    else if (blockIdx.z == 1) { W = w_k; bias = b_k; C = g_kbuf; }
    else                      { W = w_v; bias = b_v; C = g_vbuf; }
    gemm_body<false>(x, x, W, bias, C, MTOT);
}

// Output projection. A rows: attention out for z<ZS, raw v for z>=ZS.
__global__ __launch_bounds__(256)
void gemm_out(const float* __restrict__ w_o, const float* __restrict__ b_o,
              float* __restrict__ out)
{
    gemm_body<true>(g_abuf, g_vbuf, w_o, b_o, out, MTOT);
}

// ---------------- rmsnorm over full DIM row (applied to q and k buffers) ----
__global__ __launch_bounds__(256)
void rmsnorm_kernel(const float* __restrict__ gq, const float* __restrict__ gk)
{
    int row = blockIdx.x;            // 0..2*MTOT-1
    float* buf;
    const float* g;
    if (row < MTOT) { buf = g_qbuf + (size_t)row * DIM; g = gq; }
    else            { buf = g_kbuf + (size_t)(row - MTOT) * DIM; g = gk; }

    int tid = threadIdx.x;
    float ss = 0.f;
    float vals[6];
#pragma unroll
    for (int i = 0; i < 6; i++) {
        vals[i] = buf[tid + i * 256];
        ss += vals[i] * vals[i];
    }
    __shared__ float sred[8];
    int lane = tid & 31, warp = tid >> 5;
#pragma unroll
    for (int off = 16; off; off >>= 1) ss += __shfl_xor_sync(0xffffffffu, ss, off);
    if (lane == 0) sred[warp] = ss;
    __syncthreads();
    if (warp == 0) {
        float v = (lane < 8) ? sred[lane] : 0.f;
#pragma unroll
        for (int off = 4; off; off >>= 1) v += __shfl_xor_sync(0xffffffffu, v, off);
        if (lane == 0) sred[0] = v;
    }
    __syncthreads();
    float inv = rsqrtf(sred[0] / (float)DIM + 1e-6f);
#pragma unroll
    for (int i = 0; i < 6; i++)
        buf[tid + i * 256] = vals[i] * inv * g[tid + i * 256];
}

// ---------------- attention: one block per (b, z<ZS, n) ----------------
__global__ __launch_bounds__(128)
void attn_kernel(const float* __restrict__ cache_k, const float* __restrict__ cache_v,
                 const float* __restrict__ rope_table,
                 const int* __restrict__ rridx, const int* __restrict__ cfi_p)
{
    const int bx = blockIdx.x;
    const int n = bx % NH;
    const int z = (bx / NH) % ZS;
    const int b = bx / (NH * ZS);

    const int tid  = threadIdx.x;
    const int lane = tid & 31;
    const int warp = tid >> 5;

    const int cfi   = cfi_p[0];
    const int slot  = cfi % FH;
    const int valid = min(cfi + 1, FH);

    __shared__ float qr[HD];
    __shared__ float prob[FH];

    // rope q with freqs_last = rope_table[cfi, z, :]
    if (tid < HD / 2) {
        int i = tid;
        float f = rope_table[((size_t)cfi * LL + z) * (HD / 2) + i];
        float c = cosf(f), s = sinf(f);
        const float* qp = g_qbuf + (((size_t)(b * LL + z)) * NH + n) * HD;
        float q0 = qp[2 * i], q1 = qp[2 * i + 1];
        qr[2 * i]     = q0 * c - q1 * s;
        qr[2 * i + 1] = q0 * s + q1 * c;
    }
    __syncthreads();

    // scores: warp per frame (strided)
    const float scale = 0.08838834764831845f;  // 1/sqrt(128)
    for (int g = warp; g < valid; g += 4) {
        const float* kp;
        if (g == slot)
            kp = g_kbuf + (((size_t)(b * LL + z)) * NH + n) * HD;
        else
            kp = cache_k + ((((size_t)b * FH + g) * LL + z) * NH + n) * HD;
        int d0 = lane * 4;
        float4 kv = *(const float4*)(kp + d0);
        int ri = rridx[g];
        const float* fp = rope_table + ((size_t)ri * LL + z) * (HD / 2) + (d0 >> 1);
        float f0 = fp[0], f1 = fp[1];
        float c0 = cosf(f0), s0 = sinf(f0);
        float c1 = cosf(f1), s1 = sinf(f1);
        float kr0 = kv.x * c0 - kv.y * s0;
        float kr1 = kv.x * s0 + kv.y * c0;
        float kr2 = kv.z * c1 - kv.w * s1;
        float kr3 = kv.z * s1 + kv.w * c1;
        float p = qr[d0] * kr0 + qr[d0 + 1] * kr1 + qr[d0 + 2] * kr2 + qr[d0 + 3] * kr3;
#pragma unroll
        for (int off = 16; off; off >>= 1) p += __shfl_xor_sync(0xffffffffu, p, off);
        if (lane == 0) prob[g] = p * scale;
    }
    __syncthreads();

    // softmax over g<valid (warp 0)
    if (warp == 0) {
        float v = (lane < valid) ? prob[lane] : -INFINITY;
        float m = v;
#pragma unroll
        for (int off = 16; off; off >>= 1) m = fmaxf(m, __shfl_xor_sync(0xffffffffu, m, off));
        float e = (lane < valid) ? expf(v - m) : 0.f;
        float ssum = e;
#pragma unroll
        for (int off = 16; off; off >>= 1) ssum += __shfl_xor_sync(0xffffffffu, ssum, off);
        if (lane < FH) prob[lane] = e / ssum;
    }
    __syncthreads();

    // output: thread per d
    int d = tid;
    float acc = 0.f;
    for (int g = 0; g < valid; g++) {
        const float* vp;
        if (g == slot)
            vp = g_vbuf + (((size_t)(b * LL + z)) * NH + n) * HD;
        else
            vp = cache_v + ((((size_t)b * FH + g) * LL + z) * NH + n) * HD;
        acc = fmaf(prob[g], vp[d], acc);
    }
    g_abuf[((size_t)(b * LL + z)) * DIM + n * HD + d] = acc;
}

// ---------------- launch ----------------
extern "C" void kernel_launch(void* const* d_in, const int* in_sizes, int n_in,
                              void* d_out, int out_size)
{
    const float* x      = (const float*)d_in[0];
    const float* w_q    = (const float*)d_in[1];
    const float* b_q    = (const float*)d_in[2];
    const float* w_k    = (const float*)d_in[3];
    const float* b_k    = (const float*)d_in[4];
    const float* w_v    = (const float*)d_in[5];
    const float* b_v    = (const float*)d_in[6];
    const float* w_o    = (const float*)d_in[7];
    const float* b_o    = (const float*)d_in[8];
    const float* g_q    = (const float*)d_in[9];
    const float* g_k    = (const float*)d_in[10];
    const float* cache_k= (const float*)d_in[11];
    const float* cache_v= (const float*)d_in[12];
    const float* rope_t = (const float*)d_in[13];
    const int*   rridx  = (const int*)d_in[14];
    const int*   cfi    = (const int*)d_in[15];
    float*       out    = (float*)d_out;

    dim3 qkvgrid(DIM / GBN, (MTOT + GBM - 1) / GBM, 3);   // (12, 18, 3)
    gemm_qkv<<<qkvgrid, 256>>>(x, w_q, b_q, w_k, b_k, w_v, b_v);

    rmsnorm_kernel<<<2 * MTOT, 256>>>(g_q, g_k);

    attn_kernel<<<BB * ZS * NH, 128>>>(cache_k, cache_v, rope_t, rridx, cfi);

    dim3 ogrid(DIM / GBN, (MTOT + GBM - 1) / GBM);        // (12, 18)
    gemm_out<<<ogrid, 256>>>(w_o, b_o, out);
}

// round 10
// speedup vs baseline: 1.5534x; 1.2570x over previous
#include <cuda_runtime.h>
#include <cuda_bf16.h>
#include <cuda_fp16.h>
#include <cstdint>
#include <cstddef>
#include <math.h>

// Problem constants (fixed by setup_inputs)
#define BB   8
#define LL   273
#define DIM  1536
#define NH   12
#define HD   128
#define ZS   256
#define FH   32
#define MTOT (BB * LL)   // 2184

// ---------------- scratch (no allocations allowed) ----------------
__device__ float  g_qbuf[(size_t)MTOT * DIM];
__device__ float  g_kbuf[(size_t)MTOT * DIM];
__device__ float  g_vbuf[(size_t)MTOT * DIM];
__device__ __half g_xh[(size_t)MTOT * DIM];          // x in fp16
__device__ __half g_ah[(size_t)MTOT * DIM];          // A of out-proj in fp16
__device__ __half g_wh[(size_t)4 * DIM * DIM];       // w_q,w_k,w_v,w_o in fp16

// ===================== FP16 GEMM, 4-stage cp.async pipeline ================
// C[m,n] = sum_k A[m,k] * W[n,k] + bias[n], fp32 accumulate.
// Block tile 128x128, BK=64 halves. 8 warps 2(m) x 4(n); warp tile 64x32.

#define GBM 128
#define GBN 128
#define BK2 64
#define SPH 72                     // padded halves per row (144 B stride)
#define TILE_H (GBM * SPH)         // halves per stage per matrix = 9216
#define NSTAGE 4
#define SMEM_BYTES2 (2 * NSTAGE * TILE_H * 2)   // 147456 B

__device__ __forceinline__ void mma_f16(float* c, const unsigned* a, const unsigned* b) {
    asm volatile(
        "mma.sync.aligned.m16n8k16.row.col.f32.f16.f16.f32 "
        "{%0,%1,%2,%3}, {%4,%5,%6,%7}, {%8,%9}, {%0,%1,%2,%3};"
        : "+f"(c[0]), "+f"(c[1]), "+f"(c[2]), "+f"(c[3])
        : "r"(a[0]), "r"(a[1]), "r"(a[2]), "r"(a[3]),
          "r"(b[0]), "r"(b[1]));
}

__device__ __forceinline__ void ldmatrix_x4(unsigned* r, unsigned addr) {
    asm volatile("ldmatrix.sync.aligned.m8n8.x4.shared.b16 {%0,%1,%2,%3}, [%4];"
                 : "=r"(r[0]), "=r"(r[1]), "=r"(r[2]), "=r"(r[3]) : "r"(addr));
}

__device__ __forceinline__ void cp_async16(unsigned dst, const void* src, int srcbytes) {
    asm volatile("cp.async.cg.shared.global [%0], [%1], 16, %2;"
                 :: "r"(dst), "l"(src), "r"(srcbytes));
}
__device__ __forceinline__ void cp_commit() {
    asm volatile("cp.async.commit_group;");
}
template <int N>
__device__ __forceinline__ void cp_wait() {
    asm volatile("cp.async.wait_group %0;" :: "n"(N));
}

__device__ __forceinline__ void gemm_body_f16(
    const __half* __restrict__ A, const __half* __restrict__ W,
    const float* __restrict__ bias, float* __restrict__ C,
    __half* __restrict__ Ch, int Mrows)
{
    extern __shared__ __half smh[];
    __half* As = smh;                         // [NSTAGE][TILE_H]
    __half* Bs = smh + NSTAGE * TILE_H;       // [NSTAGE][TILE_H]

    const int bm = blockIdx.y * GBM;
    const int bn = blockIdx.x * GBN;
    const int tid  = threadIdx.x;
    const int lane = tid & 31;
    const int warp = tid >> 5;
    const int wm = warp >> 2;
    const int wn = warp & 3;

    const int ldr  = tid >> 3;            // 0..31 base row
    const int ldc8 = (tid & 7) << 3;      // half offset within row (16B steps)

    // ---- gmem row pointers ----
    const __half* aptr[4];
    int abytes[4];
#pragma unroll
    for (int i = 0; i < 4; i++) {
        int gr = bm + ldr + i * 32;
        int ok = (gr < Mrows);
        int grc = ok ? gr : (Mrows - 1);
        aptr[i] = A + (size_t)grc * DIM + ldc8;
        abytes[i] = ok ? 16 : 0;
    }
    const __half* wptr[4];
#pragma unroll
    for (int i = 0; i < 4; i++)
        wptr[i] = W + (size_t)(bn + ldr + i * 32) * DIM + ldc8;

    const unsigned asb = (unsigned)__cvta_generic_to_shared(As);
    const unsigned bsb = (unsigned)__cvta_generic_to_shared(Bs);
    const unsigned adst = asb + (unsigned)(ldr * SPH + ldc8) * 2u;
    const unsigned bdst = bsb + (unsigned)(ldr * SPH + ldc8) * 2u;

    // ---- ldmatrix per-lane base addresses (stage 0, kk 0) ----
    const int lm = lane >> 3;
    const int lr = lane & 7;
    unsigned aaddr[4];
#pragma unroll
    for (int mt = 0; mt < 4; mt++) {
        int row = wm * 64 + mt * 16 + (lm & 1) * 8 + lr;
        int col = (lm >> 1) * 8;
        aaddr[mt] = asb + (unsigned)(row * SPH + col) * 2u;
    }
    unsigned baddr[2];
#pragma unroll
    for (int p = 0; p < 2; p++) {
        int row = wn * 32 + p * 16 + (lm >> 1) * 8 + lr;
        int col = (lm & 1) * 8;
        baddr[p] = bsb + (unsigned)(row * SPH + col) * 2u;
    }

    float acc[4][4][4];
#pragma unroll
    for (int i = 0; i < 4; i++)
#pragma unroll
        for (int j = 0; j < 4; j++)
#pragma unroll
            for (int r = 0; r < 4; r++) acc[i][j][r] = 0.f;

    const int NT = DIM / BK2;   // 24

    // ---- prologue: load tiles 0,1 ----
#pragma unroll
    for (int pt = 0; pt < 2; pt++) {
        const unsigned soff = (unsigned)(pt * TILE_H) * 2u;
        const int kt = pt * BK2;
#pragma unroll
        for (int i = 0; i < 4; i++) {
            cp_async16(adst + soff + (unsigned)(i * 32 * SPH) * 2u, aptr[i] + kt, abytes[i]);
            cp_async16(bdst + soff + (unsigned)(i * 32 * SPH) * 2u, wptr[i] + kt, 16);
        }
        cp_commit();
    }

    for (int t = 0; t < NT; t++) {
        if (t + 2 < NT) {
            const int slot = (t + 2) & 3;
            const unsigned soff = (unsigned)(slot * TILE_H) * 2u;
            const int kt = (t + 2) * BK2;
#pragma unroll
            for (int i = 0; i < 4; i++) {
                cp_async16(adst + soff + (unsigned)(i * 32 * SPH) * 2u, aptr[i] + kt, abytes[i]);
                cp_async16(bdst + soff + (unsigned)(i * 32 * SPH) * 2u, wptr[i] + kt, 16);
            }
        }
        cp_commit();      // unconditional: keeps group arithmetic exact
        cp_wait<2>();     // tile t resident
        __syncthreads();

        const unsigned soff = (unsigned)((t & 3) * TILE_H) * 2u;
#pragma unroll
        for (int kk = 0; kk < BK2 / 16; kk++) {
            const unsigned koffb = (unsigned)(kk * 16 * 2);
            unsigned afrag[4][4];
            unsigned bfrag[4][2];
#pragma unroll
            for (int mt = 0; mt < 4; mt++)
                ldmatrix_x4(afrag[mt], aaddr[mt] + soff + koffb);
#pragma unroll
            for (int p = 0; p < 2; p++) {
                unsigned v[4];
                ldmatrix_x4(v, baddr[p] + soff + koffb);
                bfrag[2 * p][0]     = v[0]; bfrag[2 * p][1]     = v[1];
                bfrag[2 * p + 1][0] = v[2]; bfrag[2 * p + 1][1] = v[3];
            }
#pragma unroll
            for (int mt = 0; mt < 4; mt++)
#pragma unroll
                for (int nt = 0; nt < 4; nt++)
                    mma_f16(acc[mt][nt], afrag[mt], bfrag[nt]);
        }
        // NOTE: no barrier here. Slot (t & 3) is only overwritten by the load
        // issued at iteration t+2, which every thread reaches only after the
        // __syncthreads() of iteration t+1 — i.e. after all warps finished
        // computing tile t.
    }

    // ---- epilogue ----
    const int rsel = lane >> 2;
    const int csel = (lane & 3) * 2;
#pragma unroll
    for (int mt = 0; mt < 4; mt++) {
#pragma unroll
        for (int nt = 0; nt < 4; nt++) {
            int col = bn + wn * 32 + nt * 8 + csel;
            float b0 = bias[col], b1 = bias[col + 1];
            int r0 = bm + wm * 64 + mt * 16 + rsel;
            if (r0 < Mrows) {
                float2 o; o.x = acc[mt][nt][0] + b0; o.y = acc[mt][nt][1] + b1;
                *(float2*)(C + (size_t)r0 * DIM + col) = o;
                if (Ch) *(__half2*)(Ch + (size_t)r0 * DIM + col) = __floats2half2_rn(o.x, o.y);
            }
            if (r0 + 8 < Mrows) {
                float2 o; o.x = acc[mt][nt][2] + b0; o.y = acc[mt][nt][3] + b1;
                *(float2*)(C + (size_t)(r0 + 8) * DIM + col) = o;
                if (Ch) *(__half2*)(Ch + (size_t)(r0 + 8) * DIM + col) = __floats2half2_rn(o.x, o.y);
            }
        }
    }
}

// ---------------- conversion kernels ----------------
__global__ __launch_bounds__(256)
void convert_x(const float* __restrict__ x)
{
    int idx = blockIdx.x * blockDim.x + threadIdx.x;
    const int n4 = MTOT * DIM / 4;
    if (idx >= n4) return;
    float4 v = *(const float4*)(x + (size_t)idx * 4);
    __half2 h01 = __floats2half2_rn(v.x, v.y);
    __half2 h23 = __floats2half2_rn(v.z, v.w);
    uint2 o; o.x = *(unsigned*)&h01; o.y = *(unsigned*)&h23;
    *(uint2*)(g_xh + (size_t)idx * 4) = o;
}

__global__ __launch_bounds__(256)
void convert_w(const float* __restrict__ w_q, const float* __restrict__ w_k,
               const float* __restrict__ w_v, const float* __restrict__ w_o)
{
    int idx = blockIdx.x * blockDim.x + threadIdx.x;
    const int n4 = DIM * DIM / 4;
    if (idx >= n4) return;
    int z = blockIdx.z;
    const float* src = (z == 0) ? w_q : (z == 1) ? w_k : (z == 2) ? w_v : w_o;
    float4 v = *(const float4*)(src + (size_t)idx * 4);
    __half2 h01 = __floats2half2_rn(v.x, v.y);
    __half2 h23 = __floats2half2_rn(v.z, v.w);
    uint2 o; o.x = *(unsigned*)&h01; o.y = *(unsigned*)&h23;
    *(uint2*)(g_wh + (size_t)z * DIM * DIM + (size_t)idx * 4) = o;
}

// ---------------- GEMM wrappers ----------------
__global__ __launch_bounds__(256)
void gemm_qkv(const float* __restrict__ b_q, const float* __restrict__ b_k,
              const float* __restrict__ b_v)
{
    const float* bias; float* C; __half* Ch;
    const __half* W = g_wh + (size_t)blockIdx.z * DIM * DIM;
    if (blockIdx.z == 0)      { bias = b_q; C = g_qbuf; Ch = nullptr; }
    else if (blockIdx.z == 1) { bias = b_k; C = g_kbuf; Ch = nullptr; }
    else                      { bias = b_v; C = g_vbuf; Ch = g_ah; }
    gemm_body_f16(g_xh, W, bias, C, Ch, MTOT);
}

__global__ __launch_bounds__(256)
void gemm_out(const float* __restrict__ b_o, float* __restrict__ out)
{
    gemm_body_f16(g_ah, g_wh + (size_t)3 * DIM * DIM, b_o, out, nullptr, MTOT);
}

// ---------------- rmsnorm over full DIM row (q and k buffers) ----
__global__ __launch_bounds__(256)
void rmsnorm_kernel(const float* __restrict__ gq, const float* __restrict__ gk)
{
    int row = blockIdx.x;            // 0..2*MTOT-1
    float* buf;
    const float* g;
    if (row < MTOT) { buf = g_qbuf + (size_t)row * DIM; g = gq; }
    else            { buf = g_kbuf + (size_t)(row - MTOT) * DIM; g = gk; }

    int tid = threadIdx.x;
    float ss = 0.f;
    float vals[6];
#pragma unroll
    for (int i = 0; i < 6; i++) {
        vals[i] = buf[tid + i * 256];
        ss += vals[i] * vals[i];
    }
    __shared__ float sred[8];
    int lane = tid & 31, warp = tid >> 5;
#pragma unroll
    for (int off = 16; off; off >>= 1) ss += __shfl_xor_sync(0xffffffffu, ss, off);
    if (lane == 0) sred[warp] = ss;
    __syncthreads();
    if (warp == 0) {
        float v = (lane < 8) ? sred[lane] : 0.f;
#pragma unroll
        for (int off = 4; off; off >>= 1) v += __shfl_xor_sync(0xffffffffu, v, off);
        if (lane == 0) sred[0] = v;
    }
    __syncthreads();
    float inv = rsqrtf(sred[0] / (float)DIM + 1e-6f);
#pragma unroll
    for (int i = 0; i < 6; i++)
        buf[tid + i * 256] = vals[i] * inv * g[tid + i * 256];
}

// ---------------- attention: one block per (b, z<ZS, n) ----------------
__global__ __launch_bounds__(128)
void attn_kernel(const float* __restrict__ cache_k, const float* __restrict__ cache_v,
                 const float* __restrict__ rope_table,
                 const int* __restrict__ rridx, const int* __restrict__ cfi_p)
{
    const int bx = blockIdx.x;
    const int n = bx % NH;
    const int z = (bx / NH) % ZS;
    const int b = bx / (NH * ZS);

    const int tid  = threadIdx.x;
    const int lane = tid & 31;
    const int warp = tid >> 5;

    const int cfi   = cfi_p[0];
    const int slot  = cfi % FH;
    const int valid = min(cfi + 1, FH);

    __shared__ float qr[HD];
    __shared__ float prob[FH];

    // rope q with freqs_last = rope_table[cfi, z, :]
    if (tid < HD / 2) {
        int i = tid;
        float f = rope_table[((size_t)cfi * LL + z) * (HD / 2) + i];
        float c = cosf(f), s = sinf(f);
        const float* qp = g_qbuf + (((size_t)(b * LL + z)) * NH + n) * HD;
        float q0 = qp[2 * i], q1 = qp[2 * i + 1];
        qr[2 * i]     = q0 * c - q1 * s;
        qr[2 * i + 1] = q0 * s + q1 * c;
    }
    __syncthreads();

    // scores: warp per frame (strided)
    const float scale = 0.08838834764831845f;  // 1/sqrt(128)
    for (int g = warp; g < valid; g += 4) {
        const float* kp;
        if (g == slot)
            kp = g_kbuf + (((size_t)(b * LL + z)) * NH + n) * HD;
        else
            kp = cache_k + ((((size_t)b * FH + g) * LL + z) * NH + n) * HD;
        int d0 = lane * 4;
        float4 kv = *(const float4*)(kp + d0);
        int ri = rridx[g];
        const float* fp = rope_table + ((size_t)ri * LL + z) * (HD / 2) + (d0 >> 1);
        float f0 = fp[0], f1 = fp[1];
        float c0 = cosf(f0), s0 = sinf(f0);
        float c1 = cosf(f1), s1 = sinf(f1);
        float kr0 = kv.x * c0 - kv.y * s0;
        float kr1 = kv.x * s0 + kv.y * c0;
        float kr2 = kv.z * c1 - kv.w * s1;
        float kr3 = kv.z * s1 + kv.w * c1;
        float p = qr[d0] * kr0 + qr[d0 + 1] * kr1 + qr[d0 + 2] * kr2 + qr[d0 + 3] * kr3;
#pragma unroll
        for (int off = 16; off; off >>= 1) p += __shfl_xor_sync(0xffffffffu, p, off);
        if (lane == 0) prob[g] = p * scale;
    }
    __syncthreads();

    // softmax over g<valid (warp 0)
    if (warp == 0) {
        float v = (lane < valid) ? prob[lane] : -INFINITY;
        float m = v;
#pragma unroll
        for (int off = 16; off; off >>= 1) m = fmaxf(m, __shfl_xor_sync(0xffffffffu, m, off));
        float e = (lane < valid) ? expf(v - m) : 0.f;
        float ssum = e;
#pragma unroll
        for (int off = 16; off; off >>= 1) ssum += __shfl_xor_sync(0xffffffffu, ssum, off);
        if (lane < FH) prob[lane] = e / ssum;
    }
    __syncthreads();

    // output: thread per d, write fp16 into g_ah
    int d = tid;
    float acc = 0.f;
    for (int g = 0; g < valid; g++) {
        const float* vp;
        if (g == slot)
            vp = g_vbuf + (((size_t)(b * LL + z)) * NH + n) * HD;
        else
            vp = cache_v + ((((size_t)b * FH + g) * LL + z) * NH + n) * HD;
        acc = fmaf(prob[g], vp[d], acc);
    }
    g_ah[((size_t)(b * LL + z)) * DIM + n * HD + d] = __float2half_rn(acc);
}

// ---------------- launch ----------------
extern "C" void kernel_launch(void* const* d_in, const int* in_sizes, int n_in,
                              void* d_out, int out_size)
{
    const float* x      = (const float*)d_in[0];
    const float* w_q    = (const float*)d_in[1];
    const float* b_q    = (const float*)d_in[2];
    const float* w_k    = (const float*)d_in[3];
    const float* b_k    = (const float*)d_in[4];
    const float* w_v    = (const float*)d_in[5];
    const float* b_v    = (const float*)d_in[6];
    const float* w_o    = (const float*)d_in[7];
    const float* b_o    = (const float*)d_in[8];
    const float* g_q    = (const float*)d_in[9];
    const float* g_k    = (const float*)d_in[10];
    const float* cache_k= (const float*)d_in[11];
    const float* cache_v= (const float*)d_in[12];
    const float* rope_t = (const float*)d_in[13];
    const int*   rridx  = (const int*)d_in[14];
    const int*   cfi    = (const int*)d_in[15];
    float*       out    = (float*)d_out;

    cudaFuncSetAttribute(gemm_qkv, cudaFuncAttributeMaxDynamicSharedMemorySize, SMEM_BYTES2);
    cudaFuncSetAttribute(gemm_out, cudaFuncAttributeMaxDynamicSharedMemorySize, SMEM_BYTES2);

    {   // x -> fp16
        const int n4 = MTOT * DIM / 4;
        convert_x<<<(n4 + 255) / 256, 256>>>(x);
    }
    {   // weights -> fp16
        const int n4 = DIM * DIM / 4;
        dim3 wgrid((n4 + 255) / 256, 1, 4);
        convert_w<<<wgrid, 256>>>(w_q, w_k, w_v, w_o);
    }

    dim3 qkvgrid(DIM / GBN, (MTOT + GBM - 1) / GBM, 3);   // (12, 18, 3)
    gemm_qkv<<<qkvgrid, 256, SMEM_BYTES2>>>(b_q, b_k, b_v);

    rmsnorm_kernel<<<2 * MTOT, 256>>>(g_q, g_k);

    attn_kernel<<<BB * ZS * NH, 128>>>(cache_k, cache_v, rope_t, rridx, cfi);

    dim3 ogrid(DIM / GBN, (MTOT + GBM - 1) / GBM);        // (12, 18)
    gemm_out<<<ogrid, 256, SMEM_BYTES2>>>(b_o, out);
}

// round 13
// speedup vs baseline: 1.6563x; 1.0662x over previous
#include <cuda_runtime.h>
#include <cuda_bf16.h>
#include <cuda_fp16.h>
#include <cstdint>
#include <cstddef>
#include <math.h>

// Problem constants (fixed by setup_inputs)
#define BB   8
#define LL   273
#define DIM  1536
#define NH   12
#define HD   128
#define ZS   256
#define FH   32
#define MTOT (BB * LL)   // 2184

// ---------------- scratch (no allocations allowed) ----------------
__device__ float  g_qbuf[(size_t)MTOT * DIM];
__device__ float  g_kbuf[(size_t)MTOT * DIM];
__device__ float  g_vbuf[(size_t)MTOT * DIM];
__device__ __half g_xh[(size_t)MTOT * DIM];          // x in fp16
__device__ __half g_ah[(size_t)MTOT * DIM];          // A of out-proj in fp16
__device__ __half g_wh[(size_t)4 * DIM * DIM];       // w_q,w_k,w_v,w_o in fp16

// ===================== FP16 GEMM, 3-stage cp.async, 2 CTA/SM ===============
// C[m,n] = sum_k A[m,k] * W[n,k] + bias[n], fp32 accumulate.
// Block tile 128x128, BK=64 halves. 8 warps 2(m) x 4(n); warp tile 64x32.

#define GBM 128
#define GBN 128
#define BK2 64
#define SPH 72                     // padded halves per row (144 B stride)
#define TILE_H (GBM * SPH)         // halves per stage per matrix = 9216
#define NSTAGE 3
#define SMEM_BYTES2 (2 * NSTAGE * TILE_H * 2)   // 110592 B -> 2 CTAs/SM

__device__ __forceinline__ void mma_f16(float* c, const unsigned* a, const unsigned* b) {
    asm volatile(
        "mma.sync.aligned.m16n8k16.row.col.f32.f16.f16.f32 "
        "{%0,%1,%2,%3}, {%4,%5,%6,%7}, {%8,%9}, {%0,%1,%2,%3};"
        : "+f"(c[0]), "+f"(c[1]), "+f"(c[2]), "+f"(c[3])
        : "r"(a[0]), "r"(a[1]), "r"(a[2]), "r"(a[3]),
          "r"(b[0]), "r"(b[1]));
}

__device__ __forceinline__ void ldmatrix_x4(unsigned* r, unsigned addr) {
    asm volatile("ldmatrix.sync.aligned.m8n8.x4.shared.b16 {%0,%1,%2,%3}, [%4];"
                 : "=r"(r[0]), "=r"(r[1]), "=r"(r[2]), "=r"(r[3]) : "r"(addr));
}

__device__ __forceinline__ void cp_async16(unsigned dst, const void* src, int srcbytes) {
    asm volatile("cp.async.cg.shared.global [%0], [%1], 16, %2;"
                 :: "r"(dst), "l"(src), "r"(srcbytes));
}
__device__ __forceinline__ void cp_commit() {
    asm volatile("cp.async.commit_group;");
}
template <int N>
__device__ __forceinline__ void cp_wait() {
    asm volatile("cp.async.wait_group %0;" :: "n"(N));
}

__device__ __forceinline__ void gemm_body_f16(
    const __half* __restrict__ A, const __half* __restrict__ W,
    const float* __restrict__ bias, float* __restrict__ C,
    __half* __restrict__ Ch, int Mrows)
{
    extern __shared__ __half smh[];
    __half* As = smh;                         // [NSTAGE][TILE_H]
    __half* Bs = smh + NSTAGE * TILE_H;       // [NSTAGE][TILE_H]

    const int bm = blockIdx.y * GBM;
    const int bn = blockIdx.x * GBN;
    const int tid  = threadIdx.x;
    const int lane = tid & 31;
    const int warp = tid >> 5;
    const int wm = warp >> 2;
    const int wn = warp & 3;

    const int ldr  = tid >> 3;            // 0..31 base row
    const int ldc8 = (tid & 7) << 3;      // half offset within row (16B steps)

    // ---- gmem row pointers ----
    const __half* aptr[4];
    int abytes[4];
#pragma unroll
    for (int i = 0; i < 4; i++) {
        int gr = bm + ldr + i * 32;
        int ok = (gr < Mrows);
        int grc = ok ? gr : (Mrows - 1);
        aptr[i] = A + (size_t)grc * DIM + ldc8;
        abytes[i] = ok ? 16 : 0;
    }
    const __half* wptr[4];
#pragma unroll
    for (int i = 0; i < 4; i++)
        wptr[i] = W + (size_t)(bn + ldr + i * 32) * DIM + ldc8;

    const unsigned asb = (unsigned)__cvta_generic_to_shared(As);
    const unsigned bsb = (unsigned)__cvta_generic_to_shared(Bs);
    const unsigned adst = asb + (unsigned)(ldr * SPH + ldc8) * 2u;
    const unsigned bdst = bsb + (unsigned)(ldr * SPH + ldc8) * 2u;

    // ---- ldmatrix per-lane base addresses (stage 0, kk 0) ----
    const int lm = lane >> 3;
    const int lr = lane & 7;
    unsigned aaddr[4];
#pragma unroll
    for (int mt = 0; mt < 4; mt++) {
        int row = wm * 64 + mt * 16 + (lm & 1) * 8 + lr;
        int col = (lm >> 1) * 8;
        aaddr[mt] = asb + (unsigned)(row * SPH + col) * 2u;
    }
    unsigned baddr[2];
#pragma unroll
    for (int p = 0; p < 2; p++) {
        int row = wn * 32 + p * 16 + (lm >> 1) * 8 + lr;
        int col = (lm & 1) * 8;
        baddr[p] = bsb + (unsigned)(row * SPH + col) * 2u;
    }

    float acc[4][4][4];
#pragma unroll
    for (int i = 0; i < 4; i++)
#pragma unroll
        for (int j = 0; j < 4; j++)
#pragma unroll
            for (int r = 0; r < 4; r++) acc[i][j][r] = 0.f;

    const int NT = DIM / BK2;   // 24

    // ---- prologue: load tiles 0,1 into stages 0,1 ----
#pragma unroll
    for (int pt = 0; pt < 2; pt++) {
        const unsigned soff = (unsigned)(pt * TILE_H) * 2u;
        const int kt = pt * BK2;
#pragma unroll
        for (int i = 0; i < 4; i++) {
            cp_async16(adst + soff + (unsigned)(i * 32 * SPH) * 2u, aptr[i] + kt, abytes[i]);
            cp_async16(bdst + soff + (unsigned)(i * 32 * SPH) * 2u, wptr[i] + kt, 16);
        }
        cp_commit();
    }

    for (int t = 0; t < NT; t++) {
        cp_wait<1>();      // group for tile t complete (one commit per iter below)
        __syncthreads();   // tile t resident CTA-wide; all warps done with tile t-1

        // issue loads for tile t+2 into slot (t+2)%3 (== slot of tile t-1, now free)
        if (t + 2 < NT) {
            const int slot = (t + 2) % NSTAGE;
            const unsigned soff = (unsigned)(slot * TILE_H) * 2u;
            const int kt = (t + 2) * BK2;
#pragma unroll
            for (int i = 0; i < 4; i++) {
                cp_async16(adst + soff + (unsigned)(i * 32 * SPH) * 2u, aptr[i] + kt, abytes[i]);
                cp_async16(bdst + soff + (unsigned)(i * 32 * SPH) * 2u, wptr[i] + kt, 16);
            }
        }
        cp_commit();       // unconditional: keeps wait-group arithmetic exact

        const unsigned soff = (unsigned)((t % NSTAGE) * TILE_H) * 2u;
#pragma unroll
        for (int kk = 0; kk < BK2 / 16; kk++) {
            const unsigned koffb = (unsigned)(kk * 16 * 2);
            unsigned afrag[4][4];
            unsigned bfrag[4][2];
#pragma unroll
            for (int mt = 0; mt < 4; mt++)
                ldmatrix_x4(afrag[mt], aaddr[mt] + soff + koffb);
#pragma unroll
            for (int p = 0; p < 2; p++) {
                unsigned v[4];
                ldmatrix_x4(v, baddr[p] + soff + koffb);
                bfrag[2 * p][0]     = v[0]; bfrag[2 * p][1]     = v[1];
                bfrag[2 * p + 1][0] = v[2]; bfrag[2 * p + 1][1] = v[3];
            }
#pragma unroll
            for (int mt = 0; mt < 4; mt++)
#pragma unroll
                for (int nt = 0; nt < 4; nt++)
                    mma_f16(acc[mt][nt], afrag[mt], bfrag[nt]);
        }
    }

    // ---- epilogue ----
    const int rsel = lane >> 2;
    const int csel = (lane & 3) * 2;
#pragma unroll
    for (int mt = 0; mt < 4; mt++) {
#pragma unroll
        for (int nt = 0; nt < 4; nt++) {
            int col = bn + wn * 32 + nt * 8 + csel;
            float b0 = bias[col], b1 = bias[col + 1];
            int r0 = bm + wm * 64 + mt * 16 + rsel;
            if (r0 < Mrows) {
                float2 o; o.x = acc[mt][nt][0] + b0; o.y = acc[mt][nt][1] + b1;
                *(float2*)(C + (size_t)r0 * DIM + col) = o;
                if (Ch) *(__half2*)(Ch + (size_t)r0 * DIM + col) = __floats2half2_rn(o.x, o.y);
            }
            if (r0 + 8 < Mrows) {
                float2 o; o.x = acc[mt][nt][2] + b0; o.y = acc[mt][nt][3] + b1;
                *(float2*)(C + (size_t)(r0 + 8) * DIM + col) = o;
                if (Ch) *(__half2*)(Ch + (size_t)(r0 + 8) * DIM + col) = __floats2half2_rn(o.x, o.y);
            }
        }
    }
}

// ---------------- conversion kernels ----------------
__global__ __launch_bounds__(256)
void convert_x(const float* __restrict__ x)
{
    int idx = blockIdx.x * blockDim.x + threadIdx.x;
    const int n4 = MTOT * DIM / 4;
    if (idx >= n4) return;
    float4 v = *(const float4*)(x + (size_t)idx * 4);
    __half2 h01 = __floats2half2_rn(v.x, v.y);
    __half2 h23 = __floats2half2_rn(v.z, v.w);
    uint2 o; o.x = *(unsigned*)&h01; o.y = *(unsigned*)&h23;
    *(uint2*)(g_xh + (size_t)idx * 4) = o;
}

__global__ __launch_bounds__(256)
void convert_w(const float* __restrict__ w_q, const float* __restrict__ w_k,
               const float* __restrict__ w_v, const float* __restrict__ w_o)
{
    int idx = blockIdx.x * blockDim.x + threadIdx.x;
    const int n4 = DIM * DIM / 4;
    if (idx >= n4) return;
    int z = blockIdx.z;
    const float* src = (z == 0) ? w_q : (z == 1) ? w_k : (z == 2) ? w_v : w_o;
    float4 v = *(const float4*)(src + (size_t)idx * 4);
    __half2 h01 = __floats2half2_rn(v.x, v.y);
    __half2 h23 = __floats2half2_rn(v.z, v.w);
    uint2 o; o.x = *(unsigned*)&h01; o.y = *(unsigned*)&h23;
    *(uint2*)(g_wh + (size_t)z * DIM * DIM + (size_t)idx * 4) = o;
}

// ---------------- GEMM wrappers ----------------
__global__ __launch_bounds__(256, 2)
void gemm_qkv(const float* __restrict__ b_q, const float* __restrict__ b_k,
              const float* __restrict__ b_v)
{
    const float* bias; float* C; __half* Ch;
    const __half* W = g_wh + (size_t)blockIdx.z * DIM * DIM;
    if (blockIdx.z == 0)      { bias = b_q; C = g_qbuf; Ch = nullptr; }
    else if (blockIdx.z == 1) { bias = b_k; C = g_kbuf; Ch = nullptr; }
    else                      { bias = b_v; C = g_vbuf; Ch = g_ah; }
    gemm_body_f16(g_xh, W, bias, C, Ch, MTOT);
}

__global__ __launch_bounds__(256, 2)
void gemm_out(const float* __restrict__ b_o, float* __restrict__ out)
{
    gemm_body_f16(g_ah, g_wh + (size_t)3 * DIM * DIM, b_o, out, nullptr, MTOT);
}

// ---------------- rmsnorm over full DIM row (q and k buffers) ----
__global__ __launch_bounds__(256)
void rmsnorm_kernel(const float* __restrict__ gq, const float* __restrict__ gk)
{
    int row = blockIdx.x;            // 0..2*MTOT-1
    float* buf;
    const float* g;
    if (row < MTOT) { buf = g_qbuf + (size_t)row * DIM; g = gq; }
    else            { buf = g_kbuf + (size_t)(row - MTOT) * DIM; g = gk; }

    int tid = threadIdx.x;
    float ss = 0.f;
    float vals[6];
#pragma unroll
    for (int i = 0; i < 6; i++) {
        vals[i] = buf[tid + i * 256];
        ss += vals[i] * vals[i];
    }
    __shared__ float sred[8];
    int lane = tid & 31, warp = tid >> 5;
#pragma unroll
    for (int off = 16; off; off >>= 1) ss += __shfl_xor_sync(0xffffffffu, ss, off);
    if (lane == 0) sred[warp] = ss;
    __syncthreads();
    if (warp == 0) {
        float v = (lane < 8) ? sred[lane] : 0.f;
#pragma unroll
        for (int off = 4; off; off >>= 1) v += __shfl_xor_sync(0xffffffffu, v, off);
        if (lane == 0) sred[0] = v;
    }
    __syncthreads();
    float inv = rsqrtf(sred[0] / (float)DIM + 1e-6f);
#pragma unroll
    for (int i = 0; i < 6; i++)
        buf[tid + i * 256] = vals[i] * inv * g[tid + i * 256];
}

// ---------------- attention: one block per (b, z<ZS, n) ----------------
__global__ __launch_bounds__(128)
void attn_kernel(const float* __restrict__ cache_k, const float* __restrict__ cache_v,
                 const float* __restrict__ rope_table,
                 const int* __restrict__ rridx, const int* __restrict__ cfi_p)
{
    const int bx = blockIdx.x;
    const int n = bx % NH;
    const int z = (bx / NH) % ZS;
    const int b = bx / (NH * ZS);

    const int tid  = threadIdx.x;
    const int lane = tid & 31;
    const int warp = tid >> 5;

    const int cfi   = cfi_p[0];
    const int slot  = cfi % FH;
    const int valid = min(cfi + 1, FH);

    __shared__ float qr[HD];
    __shared__ float prob[FH];

    // rope q with freqs_last = rope_table[cfi, z, :]
    if (tid < HD / 2) {
        int i = tid;
        float f = rope_table[((size_t)cfi * LL + z) * (HD / 2) + i];
        float c = cosf(f), s = sinf(f);
        const float* qp = g_qbuf + (((size_t)(b * LL + z)) * NH + n) * HD;
        float q0 = qp[2 * i], q1 = qp[2 * i + 1];
        qr[2 * i]     = q0 * c - q1 * s;
        qr[2 * i + 1] = q0 * s + q1 * c;
    }
    __syncthreads();

    // scores: warp per frame (strided)
    const float scale = 0.08838834764831845f;  // 1/sqrt(128)
    for (int g = warp; g < valid; g += 4) {
        const float* kp;
        if (g == slot)
            kp = g_kbuf + (((size_t)(b * LL + z)) * NH + n) * HD;
        else
            kp = cache_k + ((((size_t)b * FH + g) * LL + z) * NH + n) * HD;
        int d0 = lane * 4;
        float4 kv = *(const float4*)(kp + d0);
        int ri = rridx[g];
        const float* fp = rope_table + ((size_t)ri * LL + z) * (HD / 2) + (d0 >> 1);
        float f0 = fp[0], f1 = fp[1];
        float c0 = cosf(f0), s0 = sinf(f0);
        float c1 = cosf(f1), s1 = sinf(f1);
        float kr0 = kv.x * c0 - kv.y * s0;
        float kr1 = kv.x * s0 + kv.y * c0;
        float kr2 = kv.z * c1 - kv.w * s1;
        float kr3 = kv.z * s1 + kv.w * c1;
        float p = qr[d0] * kr0 + qr[d0 + 1] * kr1 + qr[d0 + 2] * kr2 + qr[d0 + 3] * kr3;
#pragma unroll
        for (int off = 16; off; off >>= 1) p += __shfl_xor_sync(0xffffffffu, p, off);
        if (lane == 0) prob[g] = p * scale;
    }
    __syncthreads();

    // softmax over g<valid (warp 0)
    if (warp == 0) {
        float v = (lane < valid) ? prob[lane] : -INFINITY;
        float m = v;
#pragma unroll
        for (int off = 16; off; off >>= 1) m = fmaxf(m, __shfl_xor_sync(0xffffffffu, m, off));
        float e = (lane < valid) ? expf(v - m) : 0.f;
        float ssum = e;
#pragma unroll
        for (int off = 16; off; off >>= 1) ssum += __shfl_xor_sync(0xffffffffu, ssum, off);
        if (lane < FH) prob[lane] = e / ssum;
    }
    __syncthreads();

    // output: thread per d, write fp16 into g_ah
    int d = tid;
    float acc = 0.f;
    for (int g = 0; g < valid; g++) {
        const float* vp;
        if (g == slot)
            vp = g_vbuf + (((size_t)(b * LL + z)) * NH + n) * HD;
        else
            vp = cache_v + ((((size_t)b * FH + g) * LL + z) * NH + n) * HD;
        acc = fmaf(prob[g], vp[d], acc);
    }
    g_ah[((size_t)(b * LL + z)) * DIM + n * HD + d] = __float2half_rn(acc);
}

// ---------------- launch ----------------
extern "C" void kernel_launch(void* const* d_in, const int* in_sizes, int n_in,
                              void* d_out, int out_size)
{
    const float* x      = (const float*)d_in[0];
    const float* w_q    = (const float*)d_in[1];
    const float* b_q    = (const float*)d_in[2];
    const float* w_k    = (const float*)d_in[3];
    const float* b_k    = (const float*)d_in[4];
    const float* w_v    = (const float*)d_in[5];
    const float* b_v    = (const float*)d_in[6];
    const float* w_o    = (const float*)d_in[7];
    const float* b_o    = (const float*)d_in[8];
    const float* g_q    = (const float*)d_in[9];
    const float* g_k    = (const float*)d_in[10];
    const float* cache_k= (const float*)d_in[11];
    const float* cache_v= (const float*)d_in[12];
    const float* rope_t = (const float*)d_in[13];
    const int*   rridx  = (const int*)d_in[14];
    const int*   cfi    = (const int*)d_in[15];
    float*       out    = (float*)d_out;

    cudaFuncSetAttribute(gemm_qkv, cudaFuncAttributeMaxDynamicSharedMemorySize, SMEM_BYTES2);
    cudaFuncSetAttribute(gemm_out, cudaFuncAttributeMaxDynamicSharedMemorySize, SMEM_BYTES2);

    {   // x -> fp16
        const int n4 = MTOT * DIM / 4;
        convert_x<<<(n4 + 255) / 256, 256>>>(x);
    }
    {   // weights -> fp16
        const int n4 = DIM * DIM / 4;
        dim3 wgrid((n4 + 255) / 256, 1, 4);
        convert_w<<<wgrid, 256>>>(w_q, w_k, w_v, w_o);
    }

    dim3 qkvgrid(DIM / GBN, (MTOT + GBM - 1) / GBM, 3);   // (12, 18, 3)
    gemm_qkv<<<qkvgrid, 256, SMEM_BYTES2>>>(b_q, b_k, b_v);

    rmsnorm_kernel<<<2 * MTOT, 256>>>(g_q, g_k);

    attn_kernel<<<BB * ZS * NH, 128>>>(cache_k, cache_v, rope_t, rridx, cfi);

    dim3 ogrid(DIM / GBN, (MTOT + GBM - 1) / GBM);        // (12, 18)
    gemm_out<<<ogrid, 256, SMEM_BYTES2>>>(b_o, out);
}

// round 15
// speedup vs baseline: 1.8107x; 1.0933x over previous
#include <cuda_runtime.h>
#include <cuda_bf16.h>
#include <cuda_fp16.h>
#include <cstdint>
#include <cstddef>
#include <math.h>

// Problem constants (fixed by setup_inputs)
#define BB   8
#define LL   273
#define DIM  1536
#define NH   12
#define HD   128
#define ZS   256
#define FH   32
#define MTOT (BB * LL)   // 2184

// ---------------- scratch (no allocations allowed) ----------------
__device__ float  g_qbuf[(size_t)MTOT * DIM];
__device__ float  g_kbuf[(size_t)MTOT * DIM];
__device__ float  g_vbuf[(size_t)MTOT * DIM];
__device__ __half g_xh[(size_t)MTOT * DIM];          // x in fp16
__device__ __half g_ah[(size_t)MTOT * DIM];          // A of out-proj in fp16
__device__ __half g_wh[(size_t)4 * DIM * DIM];       // w_q,w_k,w_v,w_o in fp16
__device__ float2 g_cs[(size_t)FH * ZS * (HD / 2)];  // cos/sin for K rope per frame
__device__ float2 g_csq[(size_t)ZS * (HD / 2)];      // cos/sin for q rope (frame cfi)

// ===================== FP16 GEMM, 3-stage cp.async, 2 CTA/SM ===============
// C[m,n] = sum_k A[m,k] * W[n,k] + bias[n], fp32 accumulate.
// Block tile 128x128, BK=64 halves. 8 warps 2(m) x 4(n); warp tile 64x32.

#define GBM 128
#define GBN 128
#define BK2 64
#define SPH 72                     // padded halves per row (144 B stride)
#define TILE_H (GBM * SPH)         // halves per stage per matrix = 9216
#define NSTAGE 3
#define SMEM_BYTES2 (2 * NSTAGE * TILE_H * 2)   // 110592 B -> 2 CTAs/SM

__device__ __forceinline__ void mma_f16(float* c, const unsigned* a, const unsigned* b) {
    asm volatile(
        "mma.sync.aligned.m16n8k16.row.col.f32.f16.f16.f32 "
        "{%0,%1,%2,%3}, {%4,%5,%6,%7}, {%8,%9}, {%0,%1,%2,%3};"
        : "+f"(c[0]), "+f"(c[1]), "+f"(c[2]), "+f"(c[3])
        : "r"(a[0]), "r"(a[1]), "r"(a[2]), "r"(a[3]),
          "r"(b[0]), "r"(b[1]));
}

__device__ __forceinline__ void ldmatrix_x4(unsigned* r, unsigned addr) {
    asm volatile("ldmatrix.sync.aligned.m8n8.x4.shared.b16 {%0,%1,%2,%3}, [%4];"
                 : "=r"(r[0]), "=r"(r[1]), "=r"(r[2]), "=r"(r[3]) : "r"(addr));
}

__device__ __forceinline__ void cp_async16(unsigned dst, const void* src, int srcbytes) {
    asm volatile("cp.async.cg.shared.global [%0], [%1], 16, %2;"
                 :: "r"(dst), "l"(src), "r"(srcbytes));
}
__device__ __forceinline__ void cp_commit() {
    asm volatile("cp.async.commit_group;");
}
template <int N>
__device__ __forceinline__ void cp_wait() {
    asm volatile("cp.async.wait_group %0;" :: "n"(N));
}

__device__ __forceinline__ void gemm_body_f16(
    const __half* __restrict__ A, const __half* __restrict__ W,
    const float* __restrict__ bias, float* __restrict__ C,
    __half* __restrict__ Ch, int Mrows)
{
    extern __shared__ __half smh[];
    __half* As = smh;                         // [NSTAGE][TILE_H]
    __half* Bs = smh + NSTAGE * TILE_H;       // [NSTAGE][TILE_H]

    const int bm = blockIdx.y * GBM;
    const int bn = blockIdx.x * GBN;
    const int tid  = threadIdx.x;
    const int lane = tid & 31;
    const int warp = tid >> 5;
    const int wm = warp >> 2;
    const int wn = warp & 3;

    const int ldr  = tid >> 3;            // 0..31 base row
    const int ldc8 = (tid & 7) << 3;      // half offset within row (16B steps)

    // ---- gmem row pointers ----
    const __half* aptr[4];
    int abytes[4];
#pragma unroll
    for (int i = 0; i < 4; i++) {
        int gr = bm + ldr + i * 32;
        int ok = (gr < Mrows);
        int grc = ok ? gr : (Mrows - 1);
        aptr[i] = A + (size_t)grc * DIM + ldc8;
        abytes[i] = ok ? 16 : 0;
    }
    const __half* wptr[4];
#pragma unroll
    for (int i = 0; i < 4; i++)
        wptr[i] = W + (size_t)(bn + ldr + i * 32) * DIM + ldc8;

    const unsigned asb = (unsigned)__cvta_generic_to_shared(As);
    const unsigned bsb = (unsigned)__cvta_generic_to_shared(Bs);
    const unsigned adst = asb + (unsigned)(ldr * SPH + ldc8) * 2u;
    const unsigned bdst = bsb + (unsigned)(ldr * SPH + ldc8) * 2u;

    // ---- ldmatrix per-lane base addresses (stage 0, kk 0) ----
    const int lm = lane >> 3;
    const int lr = lane & 7;
    unsigned aaddr[4];
#pragma unroll
    for (int mt = 0; mt < 4; mt++) {
        int row = wm * 64 + mt * 16 + (lm & 1) * 8 + lr;
        int col = (lm >> 1) * 8;
        aaddr[mt] = asb + (unsigned)(row * SPH + col) * 2u;
    }
    unsigned baddr[2];
#pragma unroll
    for (int p = 0; p < 2; p++) {
        int row = wn * 32 + p * 16 + (lm >> 1) * 8 + lr;
        int col = (lm & 1) * 8;
        baddr[p] = bsb + (unsigned)(row * SPH + col) * 2u;
    }

    float acc[4][4][4];
#pragma unroll
    for (int i = 0; i < 4; i++)
#pragma unroll
        for (int j = 0; j < 4; j++)
#pragma unroll
            for (int r = 0; r < 4; r++) acc[i][j][r] = 0.f;

    const int NT = DIM / BK2;   // 24

    // ---- prologue: load tiles 0,1 into stages 0,1 ----
#pragma unroll
    for (int pt = 0; pt < 2; pt++) {
        const unsigned soff = (unsigned)(pt * TILE_H) * 2u;
        const int kt = pt * BK2;
#pragma unroll
        for (int i = 0; i < 4; i++) {
            cp_async16(adst + soff + (unsigned)(i * 32 * SPH) * 2u, aptr[i] + kt, abytes[i]);
            cp_async16(bdst + soff + (unsigned)(i * 32 * SPH) * 2u, wptr[i] + kt, 16);
        }
        cp_commit();
    }

    for (int t = 0; t < NT; t++) {
        cp_wait<1>();      // group for tile t complete (one commit per iter below)
        __syncthreads();   // tile t resident CTA-wide; all warps done with tile t-1

        // issue loads for tile t+2 into slot (t+2)%3 (== slot of tile t-1, now free)
        if (t + 2 < NT) {
            const int slot = (t + 2) % NSTAGE;
            const unsigned soff = (unsigned)(slot * TILE_H) * 2u;
            const int kt = (t + 2) * BK2;
#pragma unroll
            for (int i = 0; i < 4; i++) {
                cp_async16(adst + soff + (unsigned)(i * 32 * SPH) * 2u, aptr[i] + kt, abytes[i]);
                cp_async16(bdst + soff + (unsigned)(i * 32 * SPH) * 2u, wptr[i] + kt, 16);
            }
        }
        cp_commit();       // unconditional: keeps wait-group arithmetic exact

        const unsigned soff = (unsigned)((t % NSTAGE) * TILE_H) * 2u;
#pragma unroll
        for (int kk = 0; kk < BK2 / 16; kk++) {
            const unsigned koffb = (unsigned)(kk * 16 * 2);
            unsigned afrag[4][4];
            unsigned bfrag[4][2];
#pragma unroll
            for (int mt = 0; mt < 4; mt++)
                ldmatrix_x4(afrag[mt], aaddr[mt] + soff + koffb);
#pragma unroll
            for (int p = 0; p < 2; p++) {
                unsigned v[4];
                ldmatrix_x4(v, baddr[p] + soff + koffb);
                bfrag[2 * p][0]     = v[0]; bfrag[2 * p][1]     = v[1];
                bfrag[2 * p + 1][0] = v[2]; bfrag[2 * p + 1][1] = v[3];
            }
#pragma unroll
            for (int mt = 0; mt < 4; mt++)
#pragma unroll
                for (int nt = 0; nt < 4; nt++)
                    mma_f16(acc[mt][nt], afrag[mt], bfrag[nt]);
        }
    }

    // ---- epilogue ----
    const int rsel = lane >> 2;
    const int csel = (lane & 3) * 2;
#pragma unroll
    for (int mt = 0; mt < 4; mt++) {
#pragma unroll
        for (int nt = 0; nt < 4; nt++) {
            int col = bn + wn * 32 + nt * 8 + csel;
            float b0 = bias[col], b1 = bias[col + 1];
            int r0 = bm + wm * 64 + mt * 16 + rsel;
            if (r0 < Mrows) {
                float2 o; o.x = acc[mt][nt][0] + b0; o.y = acc[mt][nt][1] + b1;
                *(float2*)(C + (size_t)r0 * DIM + col) = o;
                if (Ch) *(__half2*)(Ch + (size_t)r0 * DIM + col) = __floats2half2_rn(o.x, o.y);
            }
            if (r0 + 8 < Mrows) {
                float2 o; o.x = acc[mt][nt][2] + b0; o.y = acc[mt][nt][3] + b1;
                *(float2*)(C + (size_t)(r0 + 8) * DIM + col) = o;
                if (Ch) *(__half2*)(Ch + (size_t)(r0 + 8) * DIM + col) = __floats2half2_rn(o.x, o.y);
            }
        }
    }
}

// ---------------- conversion kernels ----------------
__global__ __launch_bounds__(256)
void convert_x(const float* __restrict__ x)
{
    int idx = blockIdx.x * blockDim.x + threadIdx.x;
    const int n4 = MTOT * DIM / 4;
    if (idx >= n4) return;
    float4 v = *(const float4*)(x + (size_t)idx * 4);
    __half2 h01 = __floats2half2_rn(v.x, v.y);
    __half2 h23 = __floats2half2_rn(v.z, v.w);
    uint2 o; o.x = *(unsigned*)&h01; o.y = *(unsigned*)&h23;
    *(uint2*)(g_xh + (size_t)idx * 4) = o;
}

__global__ __launch_bounds__(256)
void convert_w(const float* __restrict__ w_q, const float* __restrict__ w_k,
               const float* __restrict__ w_v, const float* __restrict__ w_o)
{
    int idx = blockIdx.x * blockDim.x + threadIdx.x;
    const int n4 = DIM * DIM / 4;
    if (idx >= n4) return;
    int z = blockIdx.z;
    const float* src = (z == 0) ? w_q : (z == 1) ? w_k : (z == 2) ? w_v : w_o;
    float4 v = *(const float4*)(src + (size_t)idx * 4);
    __half2 h01 = __floats2half2_rn(v.x, v.y);
    __half2 h23 = __floats2half2_rn(v.z, v.w);
    uint2 o; o.x = *(unsigned*)&h01; o.y = *(unsigned*)&h23;
    *(uint2*)(g_wh + (size_t)z * DIM * DIM + (size_t)idx * 4) = o;
}

// ---------------- rope cos/sin table precompute ----------------
// g_cs[g][z][i]  = (cos, sin) of rope_table[rridx[g], z, i]   (K frames)
// g_csq[z][i]    = (cos, sin) of rope_table[cfi, z, i]        (q)
__global__ __launch_bounds__(256)
void rope_tables(const float* __restrict__ rope_table,
                 const int* __restrict__ rridx, const int* __restrict__ cfi_p)
{
    const int HP = HD / 2;
    int idx = blockIdx.x * blockDim.x + threadIdx.x;
    const int nk = FH * ZS * HP;
    const int nq = ZS * HP;
    if (idx < nk) {
        int g = idx / (ZS * HP);
        int rem = idx % (ZS * HP);
        int z = rem / HP;
        int i = rem % HP;
        int ri = rridx[g];
        float f = rope_table[((size_t)ri * LL + z) * HP + i];
        float s, c;
        __sincosf(f, &s, &c);   // fast HW path; rope angles are in [0, 2pi)
        g_cs[idx] = make_float2(c, s);
    } else if (idx < nk + nq) {
        int j = idx - nk;
        int z = j / HP;
        int i = j % HP;
        float f = rope_table[((size_t)cfi_p[0] * LL + z) * HP + i];
        float s, c;
        __sincosf(f, &s, &c);
        g_csq[j] = make_float2(c, s);
    }
}

// ---------------- GEMM wrappers ----------------
__global__ __launch_bounds__(256, 2)
void gemm_qkv(const float* __restrict__ b_q, const float* __restrict__ b_k,
              const float* __restrict__ b_v)
{
    const float* bias; float* C; __half* Ch;
    const __half* W = g_wh + (size_t)blockIdx.z * DIM * DIM;
    if (blockIdx.z == 0)      { bias = b_q; C = g_qbuf; Ch = nullptr; }
    else if (blockIdx.z == 1) { bias = b_k; C = g_kbuf; Ch = nullptr; }
    else                      { bias = b_v; C = g_vbuf; Ch = g_ah; }
    gemm_body_f16(g_xh, W, bias, C, Ch, MTOT);
}

__global__ __launch_bounds__(256, 2)
void gemm_out(const float* __restrict__ b_o, float* __restrict__ out)
{
    gemm_body_f16(g_ah, g_wh + (size_t)3 * DIM * DIM, b_o, out, nullptr, MTOT);
}

// ---------------- rmsnorm over full DIM row (q and k buffers) ----
__global__ __launch_bounds__(256)
void rmsnorm_kernel(const float* __restrict__ gq, const float* __restrict__ gk)
{
    int row = blockIdx.x;            // 0..2*MTOT-1
    float* buf;
    const float* g;
    if (row < MTOT) { buf = g_qbuf + (size_t)row * DIM; g = gq; }
    else            { buf = g_kbuf + (size_t)(row - MTOT) * DIM; g = gk; }

    int tid = threadIdx.x;
    float ss = 0.f;
    float vals[6];
#pragma unroll
    for (int i = 0; i < 6; i++) {
        vals[i] = buf[tid + i * 256];
        ss += vals[i] * vals[i];
    }
    __shared__ float sred[8];
    int lane = tid & 31, warp = tid >> 5;
#pragma unroll
    for (int off = 16; off; off >>= 1) ss += __shfl_xor_sync(0xffffffffu, ss, off);
    if (lane == 0) sred[warp] = ss;
    __syncthreads();
    if (warp == 0) {
        float v = (lane < 8) ? sred[lane] : 0.f;
#pragma unroll
        for (int off = 4; off; off >>= 1) v += __shfl_xor_sync(0xffffffffu, v, off);
        if (lane == 0) sred[0] = v;
    }
    __syncthreads();
    float inv = rsqrtf(sred[0] / (float)DIM + 1e-6f);
#pragma unroll
    for (int i = 0; i < 6; i++)
        buf[tid + i * 256] = vals[i] * inv * g[tid + i * 256];
}

// ---------------- attention: one block per (b, z<ZS, n) ----------------
__global__ __launch_bounds__(128)
void attn_kernel(const float* __restrict__ cache_k, const float* __restrict__ cache_v,
                 const int* __restrict__ cfi_p)
{
    const int bx = blockIdx.x;
    const int n = bx % NH;
    const int z = (bx / NH) % ZS;
    const int b = bx / (NH * ZS);

    const int tid  = threadIdx.x;
    const int lane = tid & 31;
    const int warp = tid >> 5;

    const int cfi   = cfi_p[0];
    const int slot  = cfi % FH;
    const int valid = min(cfi + 1, FH);

    __shared__ float qr[HD];
    __shared__ float prob[FH];

    // rope q with precomputed cos/sin (frame cfi)
    if (tid < HD / 2) {
        int i = tid;
        float2 cs = g_csq[z * (HD / 2) + i];
        const float* qp = g_qbuf + (((size_t)(b * LL + z)) * NH + n) * HD;
        float q0 = qp[2 * i], q1 = qp[2 * i + 1];
        qr[2 * i]     = q0 * cs.x - q1 * cs.y;
        qr[2 * i + 1] = q0 * cs.y + q1 * cs.x;
    }
    __syncthreads();

    // scores: warp per frame (strided)
    const float scale = 0.08838834764831845f;  // 1/sqrt(128)
    for (int g = warp; g < valid; g += 4) {
        const float* kp;
        if (g == slot)
            kp = g_kbuf + (((size_t)(b * LL + z)) * NH + n) * HD;
        else
            kp = cache_k + ((((size_t)b * FH + g) * LL + z) * NH + n) * HD;
        int d0 = lane * 4;
        float4 kv = *(const float4*)(kp + d0);
        // precomputed cos/sin: two pairs per lane, coalesced 16B
        const float2* csp = g_cs + ((size_t)g * ZS + z) * (HD / 2) + (d0 >> 1);
        float2 cs0 = csp[0], cs1 = csp[1];
        float kr0 = kv.x * cs0.x - kv.y * cs0.y;
        float kr1 = kv.x * cs0.y + kv.y * cs0.x;
        float kr2 = kv.z * cs1.x - kv.w * cs1.y;
        float kr3 = kv.z * cs1.y + kv.w * cs1.x;
        float p = qr[d0] * kr0 + qr[d0 + 1] * kr1 + qr[d0 + 2] * kr2 + qr[d0 + 3] * kr3;
#pragma unroll
        for (int off = 16; off; off >>= 1) p += __shfl_xor_sync(0xffffffffu, p, off);
        if (lane == 0) prob[g] = p * scale;
    }
    __syncthreads();

    // softmax over g<valid (warp 0)
    if (warp == 0) {
        float v = (lane < valid) ? prob[lane] : -INFINITY;
        float m = v;
#pragma unroll
        for (int off = 16; off; off >>= 1) m = fmaxf(m, __shfl_xor_sync(0xffffffffu, m, off));
        float e = (lane < valid) ? expf(v - m) : 0.f;
        float ssum = e;
#pragma unroll
        for (int off = 16; off; off >>= 1) ssum += __shfl_xor_sync(0xffffffffu, ssum, off);
        if (lane < FH) prob[lane] = e / ssum;
    }
    __syncthreads();

    // output: thread per d, write fp16 into g_ah
    int d = tid;
    float acc = 0.f;
    for (int g = 0; g < valid; g++) {
        const float* vp;
        if (g == slot)
            vp = g_vbuf + (((size_t)(b * LL + z)) * NH + n) * HD;
        else
            vp = cache_v + ((((size_t)b * FH + g) * LL + z) * NH + n) * HD;
        acc = fmaf(prob[g], vp[d], acc);
    }
    g_ah[((size_t)(b * LL + z)) * DIM + n * HD + d] = __float2half_rn(acc);
}

// ---------------- launch ----------------
extern "C" void kernel_launch(void* const* d_in, const int* in_sizes, int n_in,
                              void* d_out, int out_size)
{
    const float* x      = (const float*)d_in[0];
    const float* w_q    = (const float*)d_in[1];
    const float* b_q    = (const float*)d_in[2];
    const float* w_k    = (const float*)d_in[3];
    const float* b_k    = (const float*)d_in[4];
    const float* w_v    = (const float*)d_in[5];
    const float* b_v    = (const float*)d_in[6];
    const float* w_o    = (const float*)d_in[7];
    const float* b_o    = (const float*)d_in[8];
    const float* g_q    = (const float*)d_in[9];
    const float* g_k    = (const float*)d_in[10];
    const float* cache_k= (const float*)d_in[11];
    const float* cache_v= (const float*)d_in[12];
    const float* rope_t = (const float*)d_in[13];
    const int*   rridx  = (const int*)d_in[14];
    const int*   cfi    = (const int*)d_in[15];
    float*       out    = (float*)d_out;

    cudaFuncSetAttribute(gemm_qkv, cudaFuncAttributeMaxDynamicSharedMemorySize, SMEM_BYTES2);
    cudaFuncSetAttribute(gemm_out, cudaFuncAttributeMaxDynamicSharedMemorySize, SMEM_BYTES2);

    {   // x -> fp16
        const int n4 = MTOT * DIM / 4;
        convert_x<<<(n4 + 255) / 256, 256>>>(x);
    }
    {   // weights -> fp16
        const int n4 = DIM * DIM / 4;
        dim3 wgrid((n4 + 255) / 256, 1, 4);
        convert_w<<<wgrid, 256>>>(w_q, w_k, w_v, w_o);
    }
    {   // rope cos/sin tables
        const int ntot = FH * ZS * (HD / 2) + ZS * (HD / 2);
        rope_tables<<<(ntot + 255) / 256, 256>>>(rope_t, rridx, cfi);
    }

    dim3 qkvgrid(DIM / GBN, (MTOT + GBM - 1) / GBM, 3);   // (12, 18, 3)
    gemm_qkv<<<qkvgrid, 256, SMEM_BYTES2>>>(b_q, b_k, b_v);

    rmsnorm_kernel<<<2 * MTOT, 256>>>(g_q, g_k);

    attn_kernel<<<BB * ZS * NH, 128>>>(cache_k, cache_v, cfi);

    dim3 ogrid(DIM / GBN, (MTOT + GBM - 1) / GBM);        // (12, 18)
    gemm_out<<<ogrid, 256, SMEM_BYTES2>>>(b_o, out);
}

// round 17
// speedup vs baseline: 1.8703x; 1.0329x over previous
#include <cuda_runtime.h>
#include <cuda_bf16.h>
#include <cuda_fp16.h>
#include <cstdint>
#include <cstddef>
#include <math.h>

// Problem constants (fixed by setup_inputs)
#define BB   8
#define LL   273
#define DIM  1536
#define NH   12
#define HD   128
#define ZS   256
#define FH   32
#define MTOT (BB * LL)   // 2184

// ---------------- scratch (no allocations allowed) ----------------
__device__ float  g_qbuf[(size_t)MTOT * DIM];
__device__ float  g_kbuf[(size_t)MTOT * DIM];
__device__ float  g_vbuf[(size_t)MTOT * DIM];
__device__ __half g_xh[(size_t)MTOT * DIM];          // x in fp16
__device__ __half g_ah[(size_t)MTOT * DIM];          // A of out-proj in fp16
__device__ __half g_wh[(size_t)4 * DIM * DIM];       // w_q,w_k,w_v,w_o in fp16
__device__ float2 g_cs[(size_t)FH * ZS * (HD / 2)];  // cos/sin for K rope per frame
__device__ float2 g_csq[(size_t)ZS * (HD / 2)];      // cos/sin for q rope (frame cfi)

// ===================== FP16 GEMM, 3-stage cp.async, 2 CTA/SM ===============
// C[m,n] = sum_k A[m,k] * W[n,k] + bias[n], fp32 accumulate.
// Block tile 128x128, BK=64 halves. 8 warps 2(m) x 4(n); warp tile 64x32.

#define GBM 128
#define GBN 128
#define BK2 64
#define SPH 72                     // padded halves per row (144 B stride)
#define TILE_H (GBM * SPH)         // halves per stage per matrix = 9216
#define NSTAGE 3
#define SMEM_BYTES2 (2 * NSTAGE * TILE_H * 2)   // 110592 B -> 2 CTAs/SM

__device__ __forceinline__ void mma_f16(float* c, const unsigned* a, const unsigned* b) {
    asm volatile(
        "mma.sync.aligned.m16n8k16.row.col.f32.f16.f16.f32 "
        "{%0,%1,%2,%3}, {%4,%5,%6,%7}, {%8,%9}, {%0,%1,%2,%3};"
        : "+f"(c[0]), "+f"(c[1]), "+f"(c[2]), "+f"(c[3])
        : "r"(a[0]), "r"(a[1]), "r"(a[2]), "r"(a[3]),
          "r"(b[0]), "r"(b[1]));
}

__device__ __forceinline__ void ldmatrix_x4(unsigned* r, unsigned addr) {
    asm volatile("ldmatrix.sync.aligned.m8n8.x4.shared.b16 {%0,%1,%2,%3}, [%4];"
                 : "=r"(r[0]), "=r"(r[1]), "=r"(r[2]), "=r"(r[3]) : "r"(addr));
}

__device__ __forceinline__ void cp_async16(unsigned dst, const void* src, int srcbytes) {
    asm volatile("cp.async.cg.shared.global [%0], [%1], 16, %2;"
                 :: "r"(dst), "l"(src), "r"(srcbytes));
}
__device__ __forceinline__ void cp_commit() {
    asm volatile("cp.async.commit_group;");
}
template <int N>
__device__ __forceinline__ void cp_wait() {
    asm volatile("cp.async.wait_group %0;" :: "n"(N));
}

__device__ __forceinline__ void gemm_body_f16(
    const __half* __restrict__ A, const __half* __restrict__ W,
    const float* __restrict__ bias, float* __restrict__ C,
    __half* __restrict__ Ch, int Mrows)
{
    extern __shared__ __half smh[];
    __half* As = smh;                         // [NSTAGE][TILE_H]
    __half* Bs = smh + NSTAGE * TILE_H;       // [NSTAGE][TILE_H]

    const int bm = blockIdx.y * GBM;
    const int bn = blockIdx.x * GBN;
    const int tid  = threadIdx.x;
    const int lane = tid & 31;
    const int warp = tid >> 5;
    const int wm = warp >> 2;
    const int wn = warp & 3;

    const int ldr  = tid >> 3;            // 0..31 base row
    const int ldc8 = (tid & 7) << 3;      // half offset within row (16B steps)

    // ---- gmem row pointers ----
    const __half* aptr[4];
    int abytes[4];
#pragma unroll
    for (int i = 0; i < 4; i++) {
        int gr = bm + ldr + i * 32;
        int ok = (gr < Mrows);
        int grc = ok ? gr : (Mrows - 1);
        aptr[i] = A + (size_t)grc * DIM + ldc8;
        abytes[i] = ok ? 16 : 0;
    }
    const __half* wptr[4];
#pragma unroll
    for (int i = 0; i < 4; i++)
        wptr[i] = W + (size_t)(bn + ldr + i * 32) * DIM + ldc8;

    const unsigned asb = (unsigned)__cvta_generic_to_shared(As);
    const unsigned bsb = (unsigned)__cvta_generic_to_shared(Bs);
    const unsigned adst = asb + (unsigned)(ldr * SPH + ldc8) * 2u;
    const unsigned bdst = bsb + (unsigned)(ldr * SPH + ldc8) * 2u;

    // ---- ldmatrix per-lane base addresses (stage 0, kk 0) ----
    const int lm = lane >> 3;
    const int lr = lane & 7;
    unsigned aaddr[4];
#pragma unroll
    for (int mt = 0; mt < 4; mt++) {
        int row = wm * 64 + mt * 16 + (lm & 1) * 8 + lr;
        int col = (lm >> 1) * 8;
        aaddr[mt] = asb + (unsigned)(row * SPH + col) * 2u;
    }
    unsigned baddr[2];
#pragma unroll
    for (int p = 0; p < 2; p++) {
        int row = wn * 32 + p * 16 + (lm >> 1) * 8 + lr;
        int col = (lm & 1) * 8;
        baddr[p] = bsb + (unsigned)(row * SPH + col) * 2u;
    }

    float acc[4][4][4];
#pragma unroll
    for (int i = 0; i < 4; i++)
#pragma unroll
        for (int j = 0; j < 4; j++)
#pragma unroll
            for (int r = 0; r < 4; r++) acc[i][j][r] = 0.f;

    const int NT = DIM / BK2;   // 24

    // ---- prologue: load tiles 0,1 into stages 0,1 ----
#pragma unroll
    for (int pt = 0; pt < 2; pt++) {
        const unsigned soff = (unsigned)(pt * TILE_H) * 2u;
        const int kt = pt * BK2;
#pragma unroll
        for (int i = 0; i < 4; i++) {
            cp_async16(adst + soff + (unsigned)(i * 32 * SPH) * 2u, aptr[i] + kt, abytes[i]);
            cp_async16(bdst + soff + (unsigned)(i * 32 * SPH) * 2u, wptr[i] + kt, 16);
        }
        cp_commit();
    }

    for (int t = 0; t < NT; t++) {
        cp_wait<1>();      // group for tile t complete (one commit per iter below)
        __syncthreads();   // tile t resident CTA-wide; all warps done with tile t-1

        // issue loads for tile t+2 into slot (t+2)%3 (== slot of tile t-1, now free)
        if (t + 2 < NT) {
            const int slot = (t + 2) % NSTAGE;
            const unsigned soff = (unsigned)(slot * TILE_H) * 2u;
            const int kt = (t + 2) * BK2;
#pragma unroll
            for (int i = 0; i < 4; i++) {
                cp_async16(adst + soff + (unsigned)(i * 32 * SPH) * 2u, aptr[i] + kt, abytes[i]);
                cp_async16(bdst + soff + (unsigned)(i * 32 * SPH) * 2u, wptr[i] + kt, 16);
            }
        }
        cp_commit();       // unconditional: keeps wait-group arithmetic exact

        const unsigned soff = (unsigned)((t % NSTAGE) * TILE_H) * 2u;
#pragma unroll
        for (int kk = 0; kk < BK2 / 16; kk++) {
            const unsigned koffb = (unsigned)(kk * 16 * 2);
            unsigned afrag[4][4];
            unsigned bfrag[4][2];
#pragma unroll
            for (int mt = 0; mt < 4; mt++)
                ldmatrix_x4(afrag[mt], aaddr[mt] + soff + koffb);
#pragma unroll
            for (int p = 0; p < 2; p++) {
                unsigned v[4];
                ldmatrix_x4(v, baddr[p] + soff + koffb);
                bfrag[2 * p][0]     = v[0]; bfrag[2 * p][1]     = v[1];
                bfrag[2 * p + 1][0] = v[2]; bfrag[2 * p + 1][1] = v[3];
            }
#pragma unroll
            for (int mt = 0; mt < 4; mt++)
#pragma unroll
                for (int nt = 0; nt < 4; nt++)
                    mma_f16(acc[mt][nt], afrag[mt], bfrag[nt]);
        }
    }

    // ---- epilogue ----
    const int rsel = lane >> 2;
    const int csel = (lane & 3) * 2;
#pragma unroll
    for (int mt = 0; mt < 4; mt++) {
#pragma unroll
        for (int nt = 0; nt < 4; nt++) {
            int col = bn + wn * 32 + nt * 8 + csel;
            float b0 = bias[col], b1 = bias[col + 1];
            int r0 = bm + wm * 64 + mt * 16 + rsel;
            if (r0 < Mrows) {
                float2 o; o.x = acc[mt][nt][0] + b0; o.y = acc[mt][nt][1] + b1;
                *(float2*)(C + (size_t)r0 * DIM + col) = o;
                if (Ch) *(__half2*)(Ch + (size_t)r0 * DIM + col) = __floats2half2_rn(o.x, o.y);
            }
            if (r0 + 8 < Mrows) {
                float2 o; o.x = acc[mt][nt][2] + b0; o.y = acc[mt][nt][3] + b1;
                *(float2*)(C + (size_t)(r0 + 8) * DIM + col) = o;
                if (Ch) *(__half2*)(Ch + (size_t)(r0 + 8) * DIM + col) = __floats2half2_rn(o.x, o.y);
            }
        }
    }
}

// ---------------- conversion kernels ----------------
__global__ __launch_bounds__(256)
void convert_x(const float* __restrict__ x)
{
    int idx = blockIdx.x * blockDim.x + threadIdx.x;
    const int n4 = MTOT * DIM / 4;
    if (idx >= n4) return;
    float4 v = *(const float4*)(x + (size_t)idx * 4);
    __half2 h01 = __floats2half2_rn(v.x, v.y);
    __half2 h23 = __floats2half2_rn(v.z, v.w);
    uint2 o; o.x = *(unsigned*)&h01; o.y = *(unsigned*)&h23;
    *(uint2*)(g_xh + (size_t)idx * 4) = o;
}

__global__ __launch_bounds__(256)
void convert_w(const float* __restrict__ w_q, const float* __restrict__ w_k,
               const float* __restrict__ w_v, const float* __restrict__ w_o)
{
    int idx = blockIdx.x * blockDim.x + threadIdx.x;
    const int n4 = DIM * DIM / 4;
    if (idx >= n4) return;
    int z = blockIdx.z;
    const float* src = (z == 0) ? w_q : (z == 1) ? w_k : (z == 2) ? w_v : w_o;
    float4 v = *(const float4*)(src + (size_t)idx * 4);
    __half2 h01 = __floats2half2_rn(v.x, v.y);
    __half2 h23 = __floats2half2_rn(v.z, v.w);
    uint2 o; o.x = *(unsigned*)&h01; o.y = *(unsigned*)&h23;
    *(uint2*)(g_wh + (size_t)z * DIM * DIM + (size_t)idx * 4) = o;
}

// ---------------- rope cos/sin table precompute ----------------
__global__ __launch_bounds__(256)
void rope_tables(const float* __restrict__ rope_table,
                 const int* __restrict__ rridx, const int* __restrict__ cfi_p)
{
    const int HP = HD / 2;
    int idx = blockIdx.x * blockDim.x + threadIdx.x;
    const int nk = FH * ZS * HP;
    const int nq = ZS * HP;
    if (idx < nk) {
        int g = idx / (ZS * HP);
        int rem = idx % (ZS * HP);
        int z = rem / HP;
        int i = rem % HP;
        int ri = rridx[g];
        float f = rope_table[((size_t)ri * LL + z) * HP + i];
        float s, c;
        __sincosf(f, &s, &c);
        g_cs[idx] = make_float2(c, s);
    } else if (idx < nk + nq) {
        int j = idx - nk;
        int z = j / HP;
        int i = j % HP;
        float f = rope_table[((size_t)cfi_p[0] * LL + z) * HP + i];
        float s, c;
        __sincosf(f, &s, &c);
        g_csq[j] = make_float2(c, s);
    }
}

// ---------------- GEMM wrappers ----------------
__global__ __launch_bounds__(256, 2)
void gemm_qkv(const float* __restrict__ b_q, const float* __restrict__ b_k,
              const float* __restrict__ b_v)
{
    const float* bias; float* C; __half* Ch;
    const __half* W = g_wh + (size_t)blockIdx.z * DIM * DIM;
    if (blockIdx.z == 0)      { bias = b_q; C = g_qbuf; Ch = nullptr; }
    else if (blockIdx.z == 1) { bias = b_k; C = g_kbuf; Ch = nullptr; }
    else                      { bias = b_v; C = g_vbuf; Ch = g_ah; }
    gemm_body_f16(g_xh, W, bias, C, Ch, MTOT);
}

__global__ __launch_bounds__(256, 2)
void gemm_out(const float* __restrict__ b_o, float* __restrict__ out)
{
    gemm_body_f16(g_ah, g_wh + (size_t)3 * DIM * DIM, b_o, out, nullptr, MTOT);
}

// ---------------- rmsnorm over full DIM row (q and k buffers) ----
__global__ __launch_bounds__(256)
void rmsnorm_kernel(const float* __restrict__ gq, const float* __restrict__ gk)
{
    int row = blockIdx.x;            // 0..2*MTOT-1
    float* buf;
    const float* g;
    if (row < MTOT) { buf = g_qbuf + (size_t)row * DIM; g = gq; }
    else            { buf = g_kbuf + (size_t)(row - MTOT) * DIM; g = gk; }

    int tid = threadIdx.x;
    float ss = 0.f;
    float vals[6];
#pragma unroll
    for (int i = 0; i < 6; i++) {
        vals[i] = buf[tid + i * 256];
        ss += vals[i] * vals[i];
    }
    __shared__ float sred[8];
    int lane = tid & 31, warp = tid >> 5;
#pragma unroll
    for (int off = 16; off; off >>= 1) ss += __shfl_xor_sync(0xffffffffu, ss, off);
    if (lane == 0) sred[warp] = ss;
    __syncthreads();
    if (warp == 0) {
        float v = (lane < 8) ? sred[lane] : 0.f;
#pragma unroll
        for (int off = 4; off; off >>= 1) v += __shfl_xor_sync(0xffffffffu, v, off);
        if (lane == 0) sred[0] = v;
    }
    __syncthreads();
    float inv = rsqrtf(sred[0] / (float)DIM + 1e-6f);
#pragma unroll
    for (int i = 0; i < 6; i++)
        buf[tid + i * 256] = vals[i] * inv * g[tid + i * 256];
}

// ---------------- attention: one block per (b, z<ZS, n) ----------------
__global__ __launch_bounds__(128)
void attn_kernel(const float* __restrict__ cache_k, const float* __restrict__ cache_v,
                 const int* __restrict__ cfi_p)
{
    const int bx = blockIdx.x;
    const int n = bx % NH;
    const int z = (bx / NH) % ZS;
    const int b = bx / (NH * ZS);

    const int tid  = threadIdx.x;
    const int lane = tid & 31;
    const int warp = tid >> 5;

    const int cfi   = cfi_p[0];
    const int slot  = cfi % FH;
    const int valid = min(cfi + 1, FH);

    __shared__ float qr[HD];
    __shared__ float prob[FH];

    // base pointers for this (b,z,n)
    const float* fresh_k = g_kbuf + (((size_t)(b * LL + z)) * NH + n) * HD;
    const float* fresh_v = g_vbuf + (((size_t)(b * LL + z)) * NH + n) * HD;
    const float* ck = cache_k + (((size_t)b * FH * LL + z) * NH + n) * HD;
    const float* cv = cache_v + (((size_t)b * FH * LL + z) * NH + n) * HD;
    const size_t gstride = (size_t)LL * NH * HD;   // stride between frames

    // rope q with precomputed cos/sin (frame cfi)
    if (tid < HD / 2) {
        int i = tid;
        float2 cs = g_csq[z * (HD / 2) + i];
        const float* qp = g_qbuf + (((size_t)(b * LL + z)) * NH + n) * HD;
        float q0 = qp[2 * i];
        float q1 = qp[2 * i + 1];
        qr[2 * i]     = q0 * cs.x - q1 * cs.y;
        qr[2 * i + 1] = q0 * cs.y + q1 * cs.x;
    }
    __syncthreads();

    // scores: warp per frame, 2 frames in flight per warp iteration
    const float scale = 0.08838834764831845f;  // 1/sqrt(128)
    const int d0 = lane * 4;
    float q0 = qr[d0], q1 = qr[d0 + 1], q2 = qr[d0 + 2], q3 = qr[d0 + 3];
    for (int g0 = warp; g0 < valid; g0 += 8) {
        const int g1 = g0 + 4;
        const bool h1 = (g1 < valid);

        const float* kp0 = (g0 == slot) ? fresh_k : (ck + (size_t)g0 * gstride);
        const float* kp1 = h1 ? ((g1 == slot) ? fresh_k : (ck + (size_t)g1 * gstride)) : kp0;

        float4 kv0 = *(const float4*)(kp0 + d0);
        float4 kv1 = *(const float4*)(kp1 + d0);
        const float2* csp0 = g_cs + ((size_t)g0 * ZS + z) * (HD / 2) + (d0 >> 1);
        const float2* csp1 = g_cs + ((size_t)(h1 ? g1 : g0) * ZS + z) * (HD / 2) + (d0 >> 1);
        float2 a0 = csp0[0], a1 = csp0[1];
        float2 b0 = csp1[0], b1 = csp1[1];

        float p0 = q0 * (kv0.x * a0.x - kv0.y * a0.y)
                 + q1 * (kv0.x * a0.y + kv0.y * a0.x)
                 + q2 * (kv0.z * a1.x - kv0.w * a1.y)
                 + q3 * (kv0.z * a1.y + kv0.w * a1.x);
        float p1 = q0 * (kv1.x * b0.x - kv1.y * b0.y)
                 + q1 * (kv1.x * b0.y + kv1.y * b0.x)
                 + q2 * (kv1.z * b1.x - kv1.w * b1.y)
                 + q3 * (kv1.z * b1.y + kv1.w * b1.x);
#pragma unroll
        for (int off = 16; off; off >>= 1) {
            p0 += __shfl_xor_sync(0xffffffffu, p0, off);
            p1 += __shfl_xor_sync(0xffffffffu, p1, off);
        }
        if (lane == 0) {
            prob[g0] = p0 * scale;
            if (h1) prob[g1] = p1 * scale;
        }
    }
    __syncthreads();

    // softmax over g<valid (warp 0)
    if (warp == 0) {
        float v = (lane < valid) ? prob[lane] : -INFINITY;
        float m = v;
#pragma unroll
        for (int off = 16; off; off >>= 1) m = fmaxf(m, __shfl_xor_sync(0xffffffffu, m, off));
        float e = (lane < valid) ? expf(v - m) : 0.f;
        float ssum = e;
#pragma unroll
        for (int off = 16; off; off >>= 1) ssum += __shfl_xor_sync(0xffffffffu, ssum, off);
        if (lane < FH) prob[lane] = e / ssum;
    }
    __syncthreads();

    // output: thread per d, 4 frames in flight
    const int d = tid;
    float acc = 0.f;
    int g = 0;
    for (; g + 4 <= valid; g += 4) {
        const float* p0 = (g     == slot) ? fresh_v : (cv + (size_t)g       * gstride);
        const float* p1 = (g + 1 == slot) ? fresh_v : (cv + (size_t)(g + 1) * gstride);
        const float* p2 = (g + 2 == slot) ? fresh_v : (cv + (size_t)(g + 2) * gstride);
        const float* p3 = (g + 3 == slot) ? fresh_v : (cv + (size_t)(g + 3) * gstride);
        float v0 = p0[d], v1 = p1[d], v2 = p2[d], v3 = p3[d];
        float w0 = prob[g], w1 = prob[g + 1], w2 = prob[g + 2], w3 = prob[g + 3];
        acc = fmaf(w0, v0, acc);
        acc = fmaf(w1, v1, acc);
        acc = fmaf(w2, v2, acc);
        acc = fmaf(w3, v3, acc);
    }
    for (; g < valid; g++) {
        const float* vp = (g == slot) ? fresh_v : (cv + (size_t)g * gstride);
        acc = fmaf(prob[g], vp[d], acc);
    }
    g_ah[((size_t)(b * LL + z)) * DIM + n * HD + d] = __float2half_rn(acc);
}

// ---------------- launch ----------------
extern "C" void kernel_launch(void* const* d_in, const int* in_sizes, int n_in,
                              void* d_out, int out_size)
{
    const float* x      = (const float*)d_in[0];
    const float* w_q    = (const float*)d_in[1];
    const float* b_q    = (const float*)d_in[2];
    const float* w_k    = (const float*)d_in[3];
    const float* b_k    = (const float*)d_in[4];
    const float* w_v    = (const float*)d_in[5];
    const float* b_v    = (const float*)d_in[6];
    const float* w_o    = (const float*)d_in[7];
    const float* b_o    = (const float*)d_in[8];
    const float* g_q    = (const float*)d_in[9];
    const float* g_k    = (const float*)d_in[10];
    const float* cache_k= (const float*)d_in[11];
    const float* cache_v= (const float*)d_in[12];
    const float* rope_t = (const float*)d_in[13];
    const int*   rridx  = (const int*)d_in[14];
    const int*   cfi    = (const int*)d_in[15];
    float*       out    = (float*)d_out;

    cudaFuncSetAttribute(gemm_qkv, cudaFuncAttributeMaxDynamicSharedMemorySize, SMEM_BYTES2);
    cudaFuncSetAttribute(gemm_out, cudaFuncAttributeMaxDynamicSharedMemorySize, SMEM_BYTES2);

    {   // x -> fp16
        const int n4 = MTOT * DIM / 4;
        convert_x<<<(n4 + 255) / 256, 256>>>(x);
    }
    {   // weights -> fp16
        const int n4 = DIM * DIM / 4;
        dim3 wgrid((n4 + 255) / 256, 1, 4);
        convert_w<<<wgrid, 256>>>(w_q, w_k, w_v, w_o);
    }
    {   // rope cos/sin tables
        const int ntot = FH * ZS * (HD / 2) + ZS * (HD / 2);
        rope_tables<<<(ntot + 255) / 256, 256>>>(rope_t, rridx, cfi);
    }

    dim3 qkvgrid(DIM / GBN, (MTOT + GBM - 1) / GBM, 3);   // (12, 18, 3)
    gemm_qkv<<<qkvgrid, 256, SMEM_BYTES2>>>(b_q, b_k, b_v);

    rmsnorm_kernel<<<2 * MTOT, 256>>>(g_q, g_k);

    attn_kernel<<<BB * ZS * NH, 128>>>(cache_k, cache_v, cfi);

    dim3 ogrid(DIM / GBN, (MTOT + GBM - 1) / GBM);        // (12, 18)
    gemm_out<<<ogrid, 256, SMEM_BYTES2>>>(b_o, out);
}